// round 8
// baseline (speedup 1.0000x reference)
#include <cuda_runtime.h>
#include <cstdint>
#include <cstddef>

#define BATCH   8
#define NPTS    4096
#define NPOINT  1024
#define NSAMPLE 32
#define CFEAT   64
#define K0PAD   72
#define EPSV    1e-5f

constexpr int M_TOTAL = BATCH * NPOINT * NSAMPLE;   // 262144 (BN population)
constexpr int MU      = BATCH * NPTS;               // 32768 unique rows
constexpr int NEWXYZ  = BATCH * NPOINT * 3;         // 24576
constexpr int NSTATB  = MU / 128;                   // 256 partial blocks (= gemm grid.y)

// ---------------- device scratch ----------------
__device__ float g_sx[MU], g_sy[MU], g_sz[MU];      // SoA xyz
__device__ float g_Y0[(size_t)MU * 64];
__device__ float g_Y1[(size_t)MU * 128];
__device__ float g_Y2[(size_t)MU * 256];
__device__ int   g_cnt[MU];                         // occurrence histogram
__device__ int   g_idx[BATCH * NPOINT * NSAMPLE];   // selected neighbor ids (set, any order)
__device__ float g_part[2][256 * NSTATB];
__device__ float g_scale[256];
__device__ float g_shift[256];

// ---------------- helpers ----------------
__device__ __forceinline__ uint32_t cvt_tf32(float x) {
    uint32_t r; asm("cvt.rna.tf32.f32 %0, %1;" : "=r"(r) : "f"(x)); return r;
}
__device__ __forceinline__ void mma_tf32(float d[4], const uint32_t a[4], const uint32_t b[2]) {
    asm volatile("mma.sync.aligned.m16n8k8.row.col.f32.tf32.tf32.f32 "
                 "{%0,%1,%2,%3}, {%4,%5,%6,%7}, {%8,%9}, {%0,%1,%2,%3};"
                 : "+f"(d[0]), "+f"(d[1]), "+f"(d[2]), "+f"(d[3])
                 : "r"(a[0]), "r"(a[1]), "r"(a[2]), "r"(a[3]),
                   "r"(b[0]), "r"(b[1]));
}
__device__ __forceinline__ unsigned long long umin64(unsigned long long a, unsigned long long b) {
    return a < b ? a : b;
}

// ---------------- prep: zero histogram + SoA transpose of xyz ----------------
__global__ __launch_bounds__(256)
void prep_kernel(const float* __restrict__ xyz) {
    int i = blockIdx.x * 256 + threadIdx.x;
    if (i < MU) {
        g_cnt[i] = 0;
        g_sx[i] = xyz[i * 3 + 0];
        g_sy[i] = xyz[i * 3 + 1];
        g_sz[i] = xyz[i * 3 + 2];
    }
}

// ---------------- KNN via exact 2-level radix select (set semantics) ----------------
__global__ __launch_bounds__(256)
void knn_kernel(const int* __restrict__ fps, float* __restrict__ out_newxyz) {
    __shared__ int hist[256];
    __shared__ unsigned long long cand[512];
    __shared__ int sel[NSAMPLE];
    __shared__ int s_bin, s_below;
    __shared__ int s_nsel, s_ncand, s_ovf;

    const int bn   = blockIdx.x;
    const int b    = bn >> 10;
    const int base = b * NPTS;
    const int tid  = threadIdx.x;
    const int lane = tid & 31;
    const int fi = fps[bn];
    const float cx = g_sx[base + fi];
    const float cy = g_sy[base + fi];
    const float cz = g_sz[base + fi];
    if (tid == 0) {
        out_newxyz[bn * 3 + 0] = cx;
        out_newxyz[bn * 3 + 1] = cy;
        out_newxyz[bn * 3 + 2] = cz;
        s_nsel = 0; s_ncand = 0; s_ovf = 0;
    }
    if (tid < 256) hist[tid] = 0;
    __syncthreads();

    // keys in registers; d2 arithmetic order matches reference exactly.
    // pass 1 histogram: exponent byte, warp-aggregated (match_any) atomics.
    unsigned long long key[16];
    #pragma unroll
    for (int j = 0; j < 16; j++) {
        int i = tid + j * 256;
        float dx = __fsub_rn(cx, g_sx[base + i]);
        float dy = __fsub_rn(cy, g_sy[base + i]);
        float dz = __fsub_rn(cz, g_sz[base + i]);
        float d2 = __fadd_rn(__fadd_rn(__fmul_rn(dx, dx), __fmul_rn(dy, dy)), __fmul_rn(dz, dz));
        key[j] = ((unsigned long long)__float_as_uint(d2) << 32) | (unsigned)i;
        int bin = (int)(key[j] >> 55);
        unsigned mask = __match_any_sync(0xffffffffu, bin);
        int leader = __ffs(mask) - 1;
        if (lane == leader) atomicAdd(&hist[bin], __popc(mask));
    }
    __syncthreads();

    // warp 0: find exponent bin containing rank 32, count strictly below
    if (tid < 32) {
        int loc[8]; int s = 0;
        #pragma unroll
        for (int q = 0; q < 8; q++) { loc[q] = hist[lane * 8 + q]; s += loc[q]; }
        int incl = s;
        #pragma unroll
        for (int o = 1; o < 32; o <<= 1) {
            int v = __shfl_up_sync(0xffffffffu, incl, o);
            if (lane >= o) incl += v;
        }
        int excl = incl - s;
        unsigned bal = __ballot_sync(0xffffffffu, excl < NSAMPLE && NSAMPLE <= incl);
        if (lane == (int)(__ffs(bal) - 1)) {
            int c = excl;
            #pragma unroll
            for (int q = 0; q < 8; q++) {
                if (NSAMPLE <= c + loc[q]) { s_bin = lane * 8 + q; s_below = c; break; }
                c += loc[q];
            }
        }
    }
    __syncthreads();
    const int estar  = s_bin;
    const int below1 = s_below;
    if (tid < 256) hist[tid] = 0;
    __syncthreads();

    // pass 2: mantissa-byte histogram within exponent bin estar (aggregated)
    #pragma unroll
    for (int j = 0; j < 16; j++) {
        unsigned hi = (unsigned)(key[j] >> 32);
        bool pred = ((int)(hi >> 23) == estar);
        unsigned am = __ballot_sync(0xffffffffu, pred);
        if (pred) {
            int bin = (hi >> 15) & 0xFF;
            unsigned mask = __match_any_sync(am, bin);
            int leader = __ffs(mask) - 1;
            if (lane == leader) atomicAdd(&hist[bin], __popc(mask));
        }
    }
    __syncthreads();
    const int R2 = NSAMPLE - below1;
    if (tid < 32) {
        int loc[8]; int s = 0;
        #pragma unroll
        for (int q = 0; q < 8; q++) { loc[q] = hist[lane * 8 + q]; s += loc[q]; }
        int incl = s;
        #pragma unroll
        for (int o = 1; o < 32; o <<= 1) {
            int v = __shfl_up_sync(0xffffffffu, incl, o);
            if (lane >= o) incl += v;
        }
        int excl = incl - s;
        unsigned bal = __ballot_sync(0xffffffffu, excl < R2 && R2 <= incl);
        if (lane == (int)(__ffs(bal) - 1)) {
            int c = excl;
            #pragma unroll
            for (int q = 0; q < 8; q++) {
                if (R2 <= c + loc[q]) { s_bin = lane * 8 + q; s_below = c; break; }
                c += loc[q];
            }
        }
    }
    __syncthreads();
    const int mstar  = s_bin;
    const int below2 = s_below;
    const int r2     = R2 - below2;

    // direct-select strict-below prefix; boundary slice -> candidates
    // (warp-aggregated appends; output order irrelevant: set semantics)
    #pragma unroll
    for (int j = 0; j < 16; j++) {
        unsigned hi = (unsigned)(key[j] >> 32);
        int e = hi >> 23, m = (hi >> 15) & 0xFF;
        bool pl = (e < estar) || (e == estar && m < mstar);
        bool pc = (e == estar) && (m == mstar);
        unsigned bl = __ballot_sync(0xffffffffu, pl);
        if (pl) {
            int leader = __ffs(bl) - 1;
            int bpos = 0;
            if (lane == leader) bpos = atomicAdd(&s_nsel, __popc(bl));
            bpos = __shfl_sync(bl, bpos, leader);
            sel[bpos + __popc(bl & ((1u << lane) - 1))] = (int)(key[j] & 0xffffffffu);
        }
        unsigned bc = __ballot_sync(0xffffffffu, pc);
        if (pc) {
            int leader = __ffs(bc) - 1;
            int bpos = 0;
            if (lane == leader) bpos = atomicAdd(&s_ncand, __popc(bc));
            bpos = __shfl_sync(bc, bpos, leader);
            int p = bpos + __popc(bc & ((1u << lane) - 1));
            if (p < 512) cand[p] = key[j]; else s_ovf = 1;
        }
    }
    __syncthreads();

    // tiny tournament over the boundary slice (typically 1-4 entries)
    if (tid < 32) {
        int C = s_ncand < 512 ? s_ncand : 512;
        (void)s_ovf;   // >512 same-prefix keys is impossible-in-practice; C clamp keeps it safe
        for (int t = 0; t < r2; t++) {
            unsigned long long best = ~0ULL;
            for (int i = lane; i < C; i += 32) best = umin64(best, cand[i]);
            #pragma unroll
            for (int o = 16; o; o >>= 1)
                best = umin64(best, __shfl_xor_sync(0xffffffffu, best, o));
            for (int i = lane; i < C; i += 32)
                if (cand[i] == best) {                  // keys unique: one lane hits
                    cand[i] = ~0ULL;
                    sel[NSAMPLE - r2 + t] = (int)(best & 0xffffffffu);
                }
        }
    }
    __syncthreads();

    if (tid < NSAMPLE) {
        int pi = sel[tid];
        g_idx[bn * NSAMPLE + tid] = pi;
        atomicAdd(&g_cnt[b * NPTS + pi], 1);    // integer adds: deterministic
    }
}

// ---------------- TF32 GEMM on unique rows + weighted BN partials ----------------
// Double-buffered A in dynamic smem, one barrier per k-tile.
// L0: reads pts directly (channels [pts64 | xyz3 | pad]), W0 rows remapped to match.
template<int KTILES, bool AFF, bool L0>
__global__ __launch_bounds__(256)
void gemm_tf32_kernel(const float* __restrict__ X, int ldx,
                      const float* __restrict__ W, int Kvalid,
                      const float* __restrict__ bias,
                      const float* __restrict__ scl,
                      const float* __restrict__ shf,
                      float* __restrict__ Y, int OC) {
    constexpr int KTOT = KTILES * 32;
    extern __shared__ uint32_t dynsmem[];
    uint32_t* Bs = dynsmem;                    // [64][KTOT]
    uint32_t* As = dynsmem + 64 * KTOT;        // [2][128][32]

    const int tid  = threadIdx.x;
    const int lane = tid & 31;
    const int wid  = tid >> 5;
    const int wm   = wid & 3;
    const int wn   = wid >> 2;
    const int m0   = blockIdx.y * 128;
    const int oc0  = blockIdx.x * 64;
    const int g    = lane >> 2;
    const int swz  = g << 2;

    // ---- W tile (whole K) ----
    for (int idx = tid; idx < 64 * KTOT; idx += 256) {
        int oc = idx / KTOT, k = idx - oc * KTOT;
        float wv;
        if (L0) {
            if (k < 64)      wv = W[(size_t)(oc0 + oc) * 67 + 3 + k];
            else if (k < 67) wv = W[(size_t)(oc0 + oc) * 67 + (k - 64)];
            else             wv = 0.f;
        } else {
            wv = (k < Kvalid) ? W[(size_t)(oc0 + oc) * Kvalid + k] : 0.f;
        }
        Bs[oc * KTOT + (k ^ ((oc & 7) << 2))] = cvt_tf32(wv);
    }

    float acc[2][4][4];
    #pragma unroll
    for (int i = 0; i < 2; i++)
        #pragma unroll
        for (int j = 0; j < 4; j++)
            #pragma unroll
            for (int k = 0; k < 4; k++) acc[i][j][k] = 0.f;

    float4 pf[4];
    auto lda = [&](int kt) {
        #pragma unroll
        for (int it = 0; it < 4; it++) {
            int idx = tid + it * 256;
            int row = idx >> 3, q = idx & 7;
            int kk  = kt * 32 + q * 4;
            int r   = m0 + row;
            if (L0) {
                if (kk < 64)
                    pf[it] = *reinterpret_cast<const float4*>(X + (size_t)r * 64 + kk);
                else if (kk == 64)
                    pf[it] = make_float4(g_sx[r], g_sy[r], g_sz[r], 0.f);
                else
                    pf[it] = make_float4(0.f, 0.f, 0.f, 0.f);
            } else {
                pf[it] = (kk < ldx)
                    ? *reinterpret_cast<const float4*>(X + (size_t)r * ldx + kk)
                    : make_float4(0.f, 0.f, 0.f, 0.f);
            }
        }
    };
    auto sta = [&](int kt, int buf) {
        #pragma unroll
        for (int it = 0; it < 4; it++) {
            int idx = tid + it * 256;
            int row = idx >> 3, q = idx & 7;
            float4 v = pf[it];
            if (AFF) {
                int kk = kt * 32 + q * 4;
                float4 s4 = *reinterpret_cast<const float4*>(scl + kk);
                float4 h4 = *reinterpret_cast<const float4*>(shf + kk);
                v.x = fmaxf(fmaf(v.x, s4.x, h4.x), 0.f);
                v.y = fmaxf(fmaf(v.y, s4.y, h4.y), 0.f);
                v.z = fmaxf(fmaf(v.z, s4.z, h4.z), 0.f);
                v.w = fmaxf(fmaf(v.w, s4.w, h4.w), 0.f);
            }
            uint4 u;
            u.x = cvt_tf32(v.x); u.y = cvt_tf32(v.y);
            u.z = cvt_tf32(v.z); u.w = cvt_tf32(v.w);
            *reinterpret_cast<uint4*>(&As[(buf << 12) + (row << 5) + ((q * 4) ^ ((row & 7) << 2))]) = u;
        }
    };

    lda(0); sta(0, 0);
    __syncthreads();

    #pragma unroll
    for (int kt = 0; kt < KTILES; kt++) {
        if (kt + 1 < KTILES) lda(kt + 1);
        const int bufb = (kt & 1) << 12;

        #pragma unroll
        for (int kc = 0; kc < 4; kc++) {
            const int k0 = kc * 8 + (lane & 3);
            uint32_t a[2][4];
            #pragma unroll
            for (int mi = 0; mi < 2; mi++) {
                int r = wm * 32 + mi * 16 + g;
                a[mi][0] = As[bufb + (r << 5) + (k0 ^ swz)];
                a[mi][1] = As[bufb + ((r + 8) << 5) + (k0 ^ swz)];
                a[mi][2] = As[bufb + (r << 5) + ((k0 + 4) ^ swz)];
                a[mi][3] = As[bufb + ((r + 8) << 5) + ((k0 + 4) ^ swz)];
            }
            uint32_t bb[4][2];
            #pragma unroll
            for (int ni = 0; ni < 4; ni++) {
                int c = wn * 32 + ni * 8 + g;
                int kb = kt * 32;
                bb[ni][0] = Bs[c * KTOT + ((kb + k0) ^ swz)];
                bb[ni][1] = Bs[c * KTOT + ((kb + k0 + 4) ^ swz)];
            }
            #pragma unroll
            for (int mi = 0; mi < 2; mi++)
                #pragma unroll
                for (int ni = 0; ni < 4; ni++)
                    mma_tf32(acc[mi][ni], a[mi], bb[ni]);
        }
        if (kt + 1 < KTILES) {
            sta(kt + 1, (kt + 1) & 1);      // other buffer: no read-write hazard
            __syncthreads();                // single barrier per k-tile
        }
    }
    __syncthreads();   // mainloop smem reads done before sred overlay

    // ---- epilogue: +bias, store raw Y, count-weighted deterministic BN partials ----
    float (*sred)[4][64] = reinterpret_cast<float (*)[4][64]>(dynsmem);

    const int rbase = m0 + wm * 32 + g;
    float wgt[4];
    #pragma unroll
    for (int q = 0; q < 4; q++) wgt[q] = (float)g_cnt[rbase + q * 8];

    #pragma unroll
    for (int ni = 0; ni < 4; ni++) {
        int cl = wn * 32 + ni * 8 + 2 * (lane & 3);
        int c  = oc0 + cl;
        float b0 = bias[c], b1 = bias[c + 1];
        float s0 = 0.f, q0 = 0.f, s1 = 0.f, q1 = 0.f;
        #pragma unroll
        for (int mi = 0; mi < 2; mi++) {
            int r = m0 + wm * 32 + mi * 16 + g;
            float wA = wgt[mi * 2], wB = wgt[mi * 2 + 1];
            float v00 = acc[mi][ni][0] + b0;
            float v01 = acc[mi][ni][1] + b1;
            float v10 = acc[mi][ni][2] + b0;
            float v11 = acc[mi][ni][3] + b1;
            *reinterpret_cast<float2*>(Y + (size_t)r * OC + c)       = make_float2(v00, v01);
            *reinterpret_cast<float2*>(Y + (size_t)(r + 8) * OC + c) = make_float2(v10, v11);
            s0 += wA * v00 + wB * v10;  q0 += wA * v00 * v00 + wB * v10 * v10;
            s1 += wA * v01 + wB * v11;  q1 += wA * v01 * v01 + wB * v11 * v11;
        }
        #pragma unroll
        for (int o = 4; o < 32; o <<= 1) {
            s0 += __shfl_xor_sync(0xffffffffu, s0, o);
            q0 += __shfl_xor_sync(0xffffffffu, q0, o);
            s1 += __shfl_xor_sync(0xffffffffu, s1, o);
            q1 += __shfl_xor_sync(0xffffffffu, q1, o);
        }
        if (g == 0) {
            sred[0][wm][cl]     = s0;
            sred[1][wm][cl]     = q0;
            sred[0][wm][cl + 1] = s1;
            sred[1][wm][cl + 1] = q1;
        }
    }
    __syncthreads();
    if (tid < 128) {
        int part = tid >> 6, c = tid & 63;
        float s = sred[part][0][c] + sred[part][1][c] + sred[part][2][c] + sred[part][3][c];
        g_part[part][(size_t)(oc0 + c) * NSTATB + blockIdx.y] = s;
    }
}

// ---------------- stats stage 2: mean/var over gathered population ----------------
__global__ __launch_bounds__(256)
void stats_final_kernel(const float* __restrict__ gamma, const float* __restrict__ beta) {
    const int oc  = blockIdx.x;
    const int tid = threadIdx.x;
    float s = 0.f, s2 = 0.f;
    for (int i = tid; i < NSTATB; i += 256) {
        s  += g_part[0][(size_t)oc * NSTATB + i];
        s2 += g_part[1][(size_t)oc * NSTATB + i];
    }
    __shared__ float sh[2][256];
    sh[0][tid] = s; sh[1][tid] = s2;
    __syncthreads();
    for (int off = 128; off; off >>= 1) {
        if (tid < off) {
            sh[0][tid] += sh[0][tid + off];
            sh[1][tid] += sh[1][tid + off];
        }
        __syncthreads();
    }
    if (tid == 0) {
        float inv  = 1.0f / (float)M_TOTAL;
        float mean = sh[0][0] * inv;
        float var  = sh[1][0] * inv - mean * mean;
        float sc   = gamma[oc] / sqrtf(var + EPSV);
        g_scale[oc] = sc;
        g_shift[oc] = beta[oc] - mean * sc;
    }
}

// ---------------- final: gather Y2 rows, BN+ReLU, max over 32 samples ----------------
__global__ __launch_bounds__(256)
void maxpool_kernel(const float* __restrict__ Y2, float* __restrict__ outp) {
    __shared__ int sidx[NSAMPLE];
    const int bn  = blockIdx.x;
    const int b   = bn >> 10;
    const int tid = threadIdx.x;
    if (tid < NSAMPLE) sidx[tid] = g_idx[bn * NSAMPLE + tid];
    __syncthreads();
    const float sc = g_scale[tid], sh = g_shift[tid];
    float m = -3.4e38f;
    #pragma unroll
    for (int s = 0; s < NSAMPLE; s++) {
        size_t row = (size_t)(b * NPTS + sidx[s]);
        float v = fmaxf(fmaf(Y2[row * 256 + tid], sc, sh), 0.f);
        m = fmaxf(m, v);
    }
    outp[(size_t)bn * 256 + tid] = m;
}

// ---------------- launch ----------------
extern "C" void kernel_launch(void* const* d_in, const int* in_sizes, int n_in,
                              void* d_out, int out_size) {
    (void)in_sizes; (void)n_in; (void)out_size;
    const float* xyz = (const float*)d_in[0];
    const float* pts = (const float*)d_in[1];
    const int*   fps = (const int*)d_in[2];
    const float* w0  = (const float*)d_in[3];
    const float* b0  = (const float*)d_in[4];
    const float* gm0 = (const float*)d_in[5];
    const float* bt0 = (const float*)d_in[6];
    const float* w1  = (const float*)d_in[7];
    const float* b1  = (const float*)d_in[8];
    const float* gm1 = (const float*)d_in[9];
    const float* bt1 = (const float*)d_in[10];
    const float* w2  = (const float*)d_in[11];
    const float* b2  = (const float*)d_in[12];
    const float* gm2 = (const float*)d_in[13];
    const float* bt2 = (const float*)d_in[14];
    float* out = (float*)d_out;

    void *pY0, *pY1, *pY2, *pSc, *pSh;
    cudaGetSymbolAddress(&pY0, g_Y0);
    cudaGetSymbolAddress(&pY1, g_Y1);
    cudaGetSymbolAddress(&pY2, g_Y2);
    cudaGetSymbolAddress(&pSc, g_scale);
    cudaGetSymbolAddress(&pSh, g_shift);
    float* Y0 = (float*)pY0;
    float* Y1 = (float*)pY1;
    float* Y2 = (float*)pY2;
    const float* Sc = (const float*)pSc;
    const float* Sh = (const float*)pSh;

    auto* k0 = gemm_tf32_kernel<3, false, true>;
    auto* k1 = gemm_tf32_kernel<2, true,  false>;
    auto* k2 = gemm_tf32_kernel<4, true,  false>;
    constexpr int SM0 = (64 * 96  + 2 * 128 * 32) * 4;   // 57344
    constexpr int SM1 = (64 * 64  + 2 * 128 * 32) * 4;   // 49152
    constexpr int SM2 = (64 * 128 + 2 * 128 * 32) * 4;   // 65536
    cudaFuncSetAttribute(k0, cudaFuncAttributeMaxDynamicSharedMemorySize, SM0);
    cudaFuncSetAttribute(k1, cudaFuncAttributeMaxDynamicSharedMemorySize, SM1);
    cudaFuncSetAttribute(k2, cudaFuncAttributeMaxDynamicSharedMemorySize, SM2);

    prep_kernel<<<(MU + 255) / 256, 256>>>(xyz);
    knn_kernel<<<BATCH * NPOINT, 256>>>(fps, out);

    k0<<<dim3(1, MU / 128), 256, SM0>>>(pts, 64, w0, 67, b0, nullptr, nullptr, Y0, 64);
    stats_final_kernel<<<64, 256>>>(gm0, bt0);

    k1<<<dim3(2, MU / 128), 256, SM1>>>(Y0, 64, w1, 64, b1, Sc, Sh, Y1, 128);
    stats_final_kernel<<<128, 256>>>(gm1, bt1);

    k2<<<dim3(4, MU / 128), 256, SM2>>>(Y1, 128, w2, 128, b2, Sc, Sh, Y2, 256);
    stats_final_kernel<<<256, 256>>>(gm2, bt2);

    maxpool_kernel<<<BATCH * NPOINT, 256>>>(Y2, out + NEWXYZ);
}

// round 9
// speedup vs baseline: 1.0417x; 1.0417x over previous
#include <cuda_runtime.h>
#include <cstdint>
#include <cstddef>

#define BATCH   8
#define NPTS    4096
#define NPOINT  1024
#define NSAMPLE 32
#define CFEAT   64
#define EPSV    1e-5f

constexpr int M_TOTAL = BATCH * NPOINT * NSAMPLE;   // 262144 (BN population)
constexpr int MU      = BATCH * NPTS;               // 32768 unique rows
constexpr int NEWXYZ  = BATCH * NPOINT * 3;         // 24576
constexpr int NSTATB  = MU / 128;                   // 256 partial blocks (= gemm grid.y)
constexpr int CPB     = 4;                          // centroids per KNN block

// ---------------- device scratch ----------------
__device__ float g_Y0[(size_t)MU * 64];
__device__ float g_Y1[(size_t)MU * 128];
__device__ float g_Y2[(size_t)MU * 256];
__device__ int   g_cnt[MU];                         // occurrence histogram
__device__ int   g_idx[BATCH * NPOINT * NSAMPLE];   // selected neighbor ids (set, any order)
__device__ float g_part[2][256 * NSTATB];
__device__ float g_scale[256];
__device__ float g_shift[256];

// ---------------- helpers ----------------
__device__ __forceinline__ uint32_t cvt_tf32(float x) {
    uint32_t r; asm("cvt.rna.tf32.f32 %0, %1;" : "=r"(r) : "f"(x)); return r;
}
__device__ __forceinline__ void mma_tf32(float d[4], const uint32_t a[4], const uint32_t b[2]) {
    asm volatile("mma.sync.aligned.m16n8k8.row.col.f32.tf32.tf32.f32 "
                 "{%0,%1,%2,%3}, {%4,%5,%6,%7}, {%8,%9}, {%0,%1,%2,%3};"
                 : "+f"(d[0]), "+f"(d[1]), "+f"(d[2]), "+f"(d[3])
                 : "r"(a[0]), "r"(a[1]), "r"(a[2]), "r"(a[3]),
                   "r"(b[0]), "r"(b[1]));
}
__device__ __forceinline__ unsigned long long umin64(unsigned long long a, unsigned long long b) {
    return a < b ? a : b;
}

// ---------------- prep: zero occurrence histogram ----------------
__global__ __launch_bounds__(256)
void prep_kernel() {
    int i = blockIdx.x * 256 + threadIdx.x;
    if (i < MU) g_cnt[i] = 0;
}

// ---------------- KNN: 4 centroids/block, smem SoA xyz, 2-level radix select ----------------
__global__ __launch_bounds__(256)
void knn_kernel(const float* __restrict__ xyz,
                const int*   __restrict__ fps,
                float*       __restrict__ out_newxyz) {
    extern __shared__ float dsm[];
    float* sx = dsm;                   // [4096]
    float* sy = sx + NPTS;             // [4096]
    float* sz = sy + NPTS;             // [4096]
    unsigned long long* cand = reinterpret_cast<unsigned long long*>(sz + NPTS);  // [512]

    __shared__ int hist[256];
    __shared__ int sel[NSAMPLE];
    __shared__ int s_bin, s_below;
    __shared__ int s_nsel, s_ncand;

    const int bn0  = blockIdx.x * CPB;
    const int b    = bn0 >> 10;
    const int base = b * NPTS;
    const int tid  = threadIdx.x;
    const int lane = tid & 31;

    // stage batch xyz: coalesced AoS read, SoA smem write
    const float* xb = xyz + (size_t)base * 3;
    for (int t = tid; t < NPTS * 3; t += 256) {
        float v = xb[t];
        int p = t / 3, c = t - p * 3;
        if (c == 0) sx[p] = v; else if (c == 1) sy[p] = v; else sz[p] = v;
    }
    __syncthreads();

    for (int cc = 0; cc < CPB; cc++) {
        const int bn = bn0 + cc;
        const int fi = fps[bn];
        const float cx = sx[fi], cy = sy[fi], cz = sz[fi];
        if (tid == 0) {
            out_newxyz[bn * 3 + 0] = cx;
            out_newxyz[bn * 3 + 1] = cy;
            out_newxyz[bn * 3 + 2] = cz;
            s_nsel = 0; s_ncand = 0;
        }
        if (tid < 256) hist[tid] = 0;
        __syncthreads();

        // keys in registers; d2 arithmetic order matches reference exactly
        unsigned long long key[16];
        #pragma unroll
        for (int j = 0; j < 16; j++) {
            int i = tid + j * 256;
            float dx = __fsub_rn(cx, sx[i]);
            float dy = __fsub_rn(cy, sy[i]);
            float dz = __fsub_rn(cz, sz[i]);
            float d2 = __fadd_rn(__fadd_rn(__fmul_rn(dx, dx), __fmul_rn(dy, dy)), __fmul_rn(dz, dz));
            key[j] = ((unsigned long long)__float_as_uint(d2) << 32) | (unsigned)i;
            atomicAdd(&hist[(unsigned)(key[j] >> 55)], 1);      // exponent byte
        }
        __syncthreads();

        // warp 0: exponent bin containing rank 32 + count strictly below
        if (tid < 32) {
            int loc[8]; int s = 0;
            #pragma unroll
            for (int q = 0; q < 8; q++) { loc[q] = hist[lane * 8 + q]; s += loc[q]; }
            int incl = s;
            #pragma unroll
            for (int o = 1; o < 32; o <<= 1) {
                int v = __shfl_up_sync(0xffffffffu, incl, o);
                if (lane >= o) incl += v;
            }
            int excl = incl - s;
            unsigned bal = __ballot_sync(0xffffffffu, excl < NSAMPLE && NSAMPLE <= incl);
            if (lane == (int)(__ffs(bal) - 1)) {
                int c = excl;
                #pragma unroll
                for (int q = 0; q < 8; q++) {
                    if (NSAMPLE <= c + loc[q]) { s_bin = lane * 8 + q; s_below = c; break; }
                    c += loc[q];
                }
            }
        }
        __syncthreads();
        const int estar  = s_bin;
        const int below1 = s_below;
        if (tid < 256) hist[tid] = 0;
        __syncthreads();

        // pass 2: mantissa-byte histogram within exponent bin estar
        #pragma unroll
        for (int j = 0; j < 16; j++) {
            unsigned hi = (unsigned)(key[j] >> 32);
            if ((int)(hi >> 23) == estar)
                atomicAdd(&hist[(hi >> 15) & 0xFF], 1);
        }
        __syncthreads();
        const int R2 = NSAMPLE - below1;
        if (tid < 32) {
            int loc[8]; int s = 0;
            #pragma unroll
            for (int q = 0; q < 8; q++) { loc[q] = hist[lane * 8 + q]; s += loc[q]; }
            int incl = s;
            #pragma unroll
            for (int o = 1; o < 32; o <<= 1) {
                int v = __shfl_up_sync(0xffffffffu, incl, o);
                if (lane >= o) incl += v;
            }
            int excl = incl - s;
            unsigned bal = __ballot_sync(0xffffffffu, excl < R2 && R2 <= incl);
            if (lane == (int)(__ffs(bal) - 1)) {
                int c = excl;
                #pragma unroll
                for (int q = 0; q < 8; q++) {
                    if (R2 <= c + loc[q]) { s_bin = lane * 8 + q; s_below = c; break; }
                    c += loc[q];
                }
            }
        }
        __syncthreads();
        const int mstar  = s_bin;
        const int below2 = s_below;
        const int r2     = R2 - below2;

        // direct-select strict-below prefix; boundary slice -> candidates
        #pragma unroll
        for (int j = 0; j < 16; j++) {
            unsigned hi = (unsigned)(key[j] >> 32);
            int e = hi >> 23, m = (hi >> 15) & 0xFF;
            if (e < estar || (e == estar && m < mstar)) {
                int p = atomicAdd(&s_nsel, 1);
                sel[p] = (int)(key[j] & 0xffffffffu);
            } else if (e == estar && m == mstar) {
                int p = atomicAdd(&s_ncand, 1);
                if (p < 512) cand[p] = key[j];
            }
        }
        __syncthreads();

        // tiny tournament over boundary slice (typically 1-4 entries)
        if (tid < 32) {
            int C = s_ncand < 512 ? s_ncand : 512;
            for (int t = 0; t < r2; t++) {
                unsigned long long best = ~0ULL;
                for (int i = lane; i < C; i += 32) best = umin64(best, cand[i]);
                #pragma unroll
                for (int o = 16; o; o >>= 1)
                    best = umin64(best, __shfl_xor_sync(0xffffffffu, best, o));
                for (int i = lane; i < C; i += 32)
                    if (cand[i] == best) {              // keys unique: one lane hits
                        cand[i] = ~0ULL;
                        sel[NSAMPLE - r2 + t] = (int)(best & 0xffffffffu);
                    }
            }
        }
        __syncthreads();

        if (tid < NSAMPLE) {
            int pi = sel[tid];
            g_idx[bn * NSAMPLE + tid] = pi;
            atomicAdd(&g_cnt[base + pi], 1);    // integer adds: deterministic
        }
        __syncthreads();    // sel/cand reused next centroid
    }
}

// ---------------- TF32 GEMM on unique rows + weighted BN partials ----------------
// R7-proven structure: static smem, XOR swizzle, reg-staged A prefetch.
// L0: A = [pts(64) | xyz(3) | pad], W0 rows remapped to match.
template<int KTILES, bool AFF, bool L0>
__global__ __launch_bounds__(256)
void gemm_tf32_kernel(const float* __restrict__ X, int ldx,
                      const float* __restrict__ xyz,
                      const float* __restrict__ W, int Kvalid,
                      const float* __restrict__ bias,
                      const float* __restrict__ scl,
                      const float* __restrict__ shf,
                      float* __restrict__ Y, int OC) {
    constexpr int KTOT = KTILES * 32;
    __shared__ uint32_t As[128][32];       // XOR-swizzled: col = k ^ ((row&7)<<2)
    __shared__ uint32_t Bs[64][KTOT];

    const int tid  = threadIdx.x;
    const int lane = tid & 31;
    const int wid  = tid >> 5;
    const int wm   = wid & 3;
    const int wn   = wid >> 2;
    const int m0   = blockIdx.y * 128;
    const int oc0  = blockIdx.x * 64;
    const int g    = lane >> 2;
    const int swz  = g << 2;

    for (int idx = tid; idx < 64 * KTOT; idx += 256) {
        int oc = idx / KTOT, k = idx - oc * KTOT;
        float wv;
        if (L0) {
            if (k < 64)      wv = W[(size_t)(oc0 + oc) * 67 + 3 + k];
            else if (k < 67) wv = W[(size_t)(oc0 + oc) * 67 + (k - 64)];
            else             wv = 0.f;
        } else {
            wv = (k < Kvalid) ? W[(size_t)(oc0 + oc) * Kvalid + k] : 0.f;
        }
        Bs[oc][k ^ ((oc & 7) << 2)] = cvt_tf32(wv);
    }

    float acc[2][4][4];
    #pragma unroll
    for (int i = 0; i < 2; i++)
        #pragma unroll
        for (int j = 0; j < 4; j++)
            #pragma unroll
            for (int k = 0; k < 4; k++) acc[i][j][k] = 0.f;

    float4 pf[4];
    auto lda = [&](int kt) {
        #pragma unroll
        for (int it = 0; it < 4; it++) {
            int idx = tid + it * 256;
            int row = idx >> 3, q = idx & 7;
            int kk  = kt * 32 + q * 4;
            int r   = m0 + row;
            if (L0) {
                if (kk < 64)
                    pf[it] = *reinterpret_cast<const float4*>(X + (size_t)r * 64 + kk);
                else if (kk == 64)
                    pf[it] = make_float4(xyz[(size_t)r * 3], xyz[(size_t)r * 3 + 1],
                                         xyz[(size_t)r * 3 + 2], 0.f);
                else
                    pf[it] = make_float4(0.f, 0.f, 0.f, 0.f);
            } else {
                pf[it] = (kk < ldx)
                    ? *reinterpret_cast<const float4*>(X + (size_t)r * ldx + kk)
                    : make_float4(0.f, 0.f, 0.f, 0.f);
            }
        }
    };
    auto sta = [&](int kt) {
        #pragma unroll
        for (int it = 0; it < 4; it++) {
            int idx = tid + it * 256;
            int row = idx >> 3, q = idx & 7;
            float4 v = pf[it];
            if (AFF) {
                int kk = kt * 32 + q * 4;
                float4 s4 = *reinterpret_cast<const float4*>(scl + kk);
                float4 h4 = *reinterpret_cast<const float4*>(shf + kk);
                v.x = fmaxf(fmaf(v.x, s4.x, h4.x), 0.f);
                v.y = fmaxf(fmaf(v.y, s4.y, h4.y), 0.f);
                v.z = fmaxf(fmaf(v.z, s4.z, h4.z), 0.f);
                v.w = fmaxf(fmaf(v.w, s4.w, h4.w), 0.f);
            }
            uint4 u;
            u.x = cvt_tf32(v.x); u.y = cvt_tf32(v.y);
            u.z = cvt_tf32(v.z); u.w = cvt_tf32(v.w);
            *reinterpret_cast<uint4*>(&As[row][(q * 4) ^ ((row & 7) << 2)]) = u;
        }
    };

    lda(0); sta(0);
    __syncthreads();

    #pragma unroll
    for (int kt = 0; kt < KTILES; kt++) {
        if (kt + 1 < KTILES) lda(kt + 1);
        #pragma unroll
        for (int kc = 0; kc < 4; kc++) {
            const int k0 = kc * 8 + (lane & 3);
            uint32_t a[2][4];
            #pragma unroll
            for (int mi = 0; mi < 2; mi++) {
                int r = wm * 32 + mi * 16 + g;
                a[mi][0] = As[r][k0 ^ swz];
                a[mi][1] = As[r + 8][k0 ^ swz];
                a[mi][2] = As[r][(k0 + 4) ^ swz];
                a[mi][3] = As[r + 8][(k0 + 4) ^ swz];
            }
            uint32_t bb[4][2];
            #pragma unroll
            for (int ni = 0; ni < 4; ni++) {
                int c = wn * 32 + ni * 8 + g;
                int kb = kt * 32;
                bb[ni][0] = Bs[c][(kb + k0) ^ swz];
                bb[ni][1] = Bs[c][(kb + k0 + 4) ^ swz];
            }
            #pragma unroll
            for (int mi = 0; mi < 2; mi++)
                #pragma unroll
                for (int ni = 0; ni < 4; ni++)
                    mma_tf32(acc[mi][ni], a[mi], bb[ni]);
        }
        __syncthreads();
        if (kt + 1 < KTILES) {
            sta(kt + 1);
            __syncthreads();
        }
    }

    // ---- epilogue: +bias, store raw Y, count-weighted deterministic BN partials ----
    float (*sred)[4][64] = reinterpret_cast<float (*)[4][64]>(&As[0][0]);

    const int rbase = m0 + wm * 32 + g;
    float wgt[4];
    #pragma unroll
    for (int q = 0; q < 4; q++) wgt[q] = (float)g_cnt[rbase + q * 8];

    #pragma unroll
    for (int ni = 0; ni < 4; ni++) {
        int cl = wn * 32 + ni * 8 + 2 * (lane & 3);
        int c  = oc0 + cl;
        float b0 = bias[c], b1 = bias[c + 1];
        float s0 = 0.f, q0 = 0.f, s1 = 0.f, q1 = 0.f;
        #pragma unroll
        for (int mi = 0; mi < 2; mi++) {
            int r = m0 + wm * 32 + mi * 16 + g;
            float wA = wgt[mi * 2], wB = wgt[mi * 2 + 1];
            float v00 = acc[mi][ni][0] + b0;
            float v01 = acc[mi][ni][1] + b1;
            float v10 = acc[mi][ni][2] + b0;
            float v11 = acc[mi][ni][3] + b1;
            *reinterpret_cast<float2*>(Y + (size_t)r * OC + c)       = make_float2(v00, v01);
            *reinterpret_cast<float2*>(Y + (size_t)(r + 8) * OC + c) = make_float2(v10, v11);
            s0 += wA * v00 + wB * v10;  q0 += wA * v00 * v00 + wB * v10 * v10;
            s1 += wA * v01 + wB * v11;  q1 += wA * v01 * v01 + wB * v11 * v11;
        }
        #pragma unroll
        for (int o = 4; o < 32; o <<= 1) {
            s0 += __shfl_xor_sync(0xffffffffu, s0, o);
            q0 += __shfl_xor_sync(0xffffffffu, q0, o);
            s1 += __shfl_xor_sync(0xffffffffu, s1, o);
            q1 += __shfl_xor_sync(0xffffffffu, q1, o);
        }
        if (g == 0) {
            sred[0][wm][cl]     = s0;
            sred[1][wm][cl]     = q0;
            sred[0][wm][cl + 1] = s1;
            sred[1][wm][cl + 1] = q1;
        }
    }
    __syncthreads();
    if (tid < 128) {
        int part = tid >> 6, c = tid & 63;
        float s = sred[part][0][c] + sred[part][1][c] + sred[part][2][c] + sred[part][3][c];
        g_part[part][(size_t)(oc0 + c) * NSTATB + blockIdx.y] = s;
    }
}

// ---------------- stats stage 2: mean/var over gathered population ----------------
__global__ __launch_bounds__(256)
void stats_final_kernel(const float* __restrict__ gamma, const float* __restrict__ beta) {
    const int oc  = blockIdx.x;
    const int tid = threadIdx.x;
    float s = 0.f, s2 = 0.f;
    for (int i = tid; i < NSTATB; i += 256) {
        s  += g_part[0][(size_t)oc * NSTATB + i];
        s2 += g_part[1][(size_t)oc * NSTATB + i];
    }
    __shared__ float sh[2][256];
    sh[0][tid] = s; sh[1][tid] = s2;
    __syncthreads();
    for (int off = 128; off; off >>= 1) {
        if (tid < off) {
            sh[0][tid] += sh[0][tid + off];
            sh[1][tid] += sh[1][tid + off];
        }
        __syncthreads();
    }
    if (tid == 0) {
        float inv  = 1.0f / (float)M_TOTAL;
        float mean = sh[0][0] * inv;
        float var  = sh[1][0] * inv - mean * mean;
        float sc   = gamma[oc] / sqrtf(var + EPSV);
        g_scale[oc] = sc;
        g_shift[oc] = beta[oc] - mean * sc;
    }
}

// ---------------- final: gather Y2 rows, BN+ReLU, max over 32 samples ----------------
__global__ __launch_bounds__(256)
void maxpool_kernel(const float* __restrict__ Y2, float* __restrict__ outp) {
    __shared__ int sidx[NSAMPLE];
    const int bn  = blockIdx.x;
    const int b   = bn >> 10;
    const int tid = threadIdx.x;
    if (tid < NSAMPLE) sidx[tid] = g_idx[bn * NSAMPLE + tid];
    __syncthreads();
    const float sc = g_scale[tid], sh = g_shift[tid];
    float m = -3.4e38f;
    #pragma unroll
    for (int s = 0; s < NSAMPLE; s++) {
        size_t row = (size_t)(b * NPTS + sidx[s]);
        float v = fmaxf(fmaf(Y2[row * 256 + tid], sc, sh), 0.f);
        m = fmaxf(m, v);
    }
    outp[(size_t)bn * 256 + tid] = m;
}

// ---------------- launch ----------------
extern "C" void kernel_launch(void* const* d_in, const int* in_sizes, int n_in,
                              void* d_out, int out_size) {
    (void)in_sizes; (void)n_in; (void)out_size;
    const float* xyz = (const float*)d_in[0];
    const float* pts = (const float*)d_in[1];
    const int*   fps = (const int*)d_in[2];
    const float* w0  = (const float*)d_in[3];
    const float* b0  = (const float*)d_in[4];
    const float* gm0 = (const float*)d_in[5];
    const float* bt0 = (const float*)d_in[6];
    const float* w1  = (const float*)d_in[7];
    const float* b1  = (const float*)d_in[8];
    const float* gm1 = (const float*)d_in[9];
    const float* bt1 = (const float*)d_in[10];
    const float* w2  = (const float*)d_in[11];
    const float* b2  = (const float*)d_in[12];
    const float* gm2 = (const float*)d_in[13];
    const float* bt2 = (const float*)d_in[14];
    float* out = (float*)d_out;

    void *pY0, *pY1, *pY2, *pSc, *pSh;
    cudaGetSymbolAddress(&pY0, g_Y0);
    cudaGetSymbolAddress(&pY1, g_Y1);
    cudaGetSymbolAddress(&pY2, g_Y2);
    cudaGetSymbolAddress(&pSc, g_scale);
    cudaGetSymbolAddress(&pSh, g_shift);
    float* Y0 = (float*)pY0;
    float* Y1 = (float*)pY1;
    float* Y2 = (float*)pY2;
    const float* Sc = (const float*)pSc;
    const float* Sh = (const float*)pSh;

    // KNN needs 52KB dynamic smem
    constexpr int KNN_SMEM = (3 * NPTS) * 4 + 512 * 8;   // 53248
    cudaFuncSetAttribute(knn_kernel, cudaFuncAttributeMaxDynamicSharedMemorySize, KNN_SMEM);

    prep_kernel<<<(MU + 255) / 256, 256>>>();
    knn_kernel<<<BATCH * NPOINT / CPB, 256, KNN_SMEM>>>(xyz, fps, out);

    gemm_tf32_kernel<3, false, true><<<dim3(1, MU / 128), 256>>>(
        pts, 64, xyz, w0, 67, b0, nullptr, nullptr, Y0, 64);
    stats_final_kernel<<<64, 256>>>(gm0, bt0);

    gemm_tf32_kernel<2, true, false><<<dim3(2, MU / 128), 256>>>(
        Y0, 64, nullptr, w1, 64, b1, Sc, Sh, Y1, 128);
    stats_final_kernel<<<128, 256>>>(gm1, bt1);

    gemm_tf32_kernel<4, true, false><<<dim3(4, MU / 128), 256>>>(
        Y1, 128, nullptr, w2, 128, b2, Sc, Sh, Y2, 256);
    stats_final_kernel<<<256, 256>>>(gm2, bt2);

    maxpool_kernel<<<BATCH * NPOINT, 256>>>(Y2, out + NEWXYZ);
}

// round 10
// speedup vs baseline: 1.0503x; 1.0083x over previous
#include <cuda_runtime.h>
#include <cstdint>
#include <cstddef>

#define BATCH   8
#define NPTS    4096
#define NPOINT  1024
#define NSAMPLE 32
#define CFEAT   64
#define K0PAD   72
#define EPSV    1e-5f

constexpr int M_TOTAL = BATCH * NPOINT * NSAMPLE;   // 262144 (BN population)
constexpr int MU      = BATCH * NPTS;               // 32768 unique rows
constexpr int NEWXYZ  = BATCH * NPOINT * 3;         // 24576
constexpr int NSTATB  = MU / 128;                   // 256 partial blocks (= gemm grid.y)

// ---------------- device scratch ----------------
__device__ float4 g_xyz4[MU];                       // packed xyz (w=0)
__device__ float g_X0[(size_t)MU * K0PAD];
__device__ float g_Y0[(size_t)MU * 64];
__device__ float g_Y1[(size_t)MU * 128];
__device__ float g_Y2[(size_t)MU * 256];
__device__ int   g_cnt[MU];                         // occurrence histogram
__device__ int   g_idx[BATCH * NPOINT * NSAMPLE];   // selected neighbor ids (set, any order)
__device__ float g_part[2][256 * NSTATB];
__device__ float g_scale[256];
__device__ float g_shift[256];

// ---------------- helpers ----------------
__device__ __forceinline__ uint32_t cvt_tf32(float x) {
    uint32_t r; asm("cvt.rna.tf32.f32 %0, %1;" : "=r"(r) : "f"(x)); return r;
}
__device__ __forceinline__ void mma_tf32(float d[4], const uint32_t a[4], const uint32_t b[2]) {
    asm volatile("mma.sync.aligned.m16n8k8.row.col.f32.tf32.tf32.f32 "
                 "{%0,%1,%2,%3}, {%4,%5,%6,%7}, {%8,%9}, {%0,%1,%2,%3};"
                 : "+f"(d[0]), "+f"(d[1]), "+f"(d[2]), "+f"(d[3])
                 : "r"(a[0]), "r"(a[1]), "r"(a[2]), "r"(a[3]),
                   "r"(b[0]), "r"(b[1]));
}
__device__ __forceinline__ unsigned long long umin64(unsigned long long a, unsigned long long b) {
    return a < b ? a : b;
}
__device__ __forceinline__ unsigned long long umax64(unsigned long long a, unsigned long long b) {
    return a > b ? a : b;
}

// ---------------- prep: zero histogram + build X0 + packed xyz ----------------
__global__ __launch_bounds__(256)
void prep_kernel(const float* __restrict__ xyz, const float* __restrict__ pts) {
    const int stride = gridDim.x * blockDim.x;
    int i = blockIdx.x * blockDim.x + threadIdx.x;
    if (i < MU) {
        g_cnt[i] = 0;
        g_xyz4[i] = make_float4(xyz[i * 3 + 0], xyz[i * 3 + 1], xyz[i * 3 + 2], 0.f);
    }
    for (int e = i; e < MU * K0PAD; e += stride) {
        int r = e / K0PAD, c = e - r * K0PAD;     // r = b*NPTS + pi
        float v = 0.f;
        if (c < 3)              v = xyz[(size_t)r * 3 + c];
        else if (c < 3 + CFEAT) v = pts[(size_t)r * CFEAT + (c - 3)];
        g_X0[e] = v;
    }
}

// ---------------- KNN via exact 2-level radix select + U-bound prefilter ----------------
// Finds the 32 smallest unique keys (d2_bits<<32|idx). Output order irrelevant.
__global__ __launch_bounds__(256)
void knn_kernel(const int* __restrict__ fps, float* __restrict__ out_newxyz) {
    __shared__ int hist[256];
    __shared__ unsigned long long cand[512];
    __shared__ unsigned long long sU[8];
    __shared__ int sel[NSAMPLE];
    __shared__ int s_bin, s_below;      // reused for both passes
    __shared__ int s_nsel, s_ncand, s_ovf;

    const int bn   = blockIdx.x;
    const int b    = bn >> 10;
    const int base = b * NPTS;
    const int tid  = threadIdx.x;
    const int lane = tid & 31;
    const int fi = fps[bn];
    const float4 cpt = g_xyz4[base + fi];
    const float cx = cpt.x, cy = cpt.y, cz = cpt.z;
    if (tid == 0) {
        out_newxyz[bn * 3 + 0] = cx;
        out_newxyz[bn * 3 + 1] = cy;
        out_newxyz[bn * 3 + 2] = cz;
        s_nsel = 0; s_ncand = 0; s_ovf = 0;
    }
    if (tid < 256) hist[tid] = 0;
    __syncthreads();

    // keys in registers; d2 arithmetic order matches reference exactly
    unsigned long long key[16];
    unsigned long long tmin = ~0ULL;
    #pragma unroll
    for (int j = 0; j < 16; j++) {
        int i = tid + j * 256;
        float4 p = g_xyz4[base + i];
        float dx = __fsub_rn(cx, p.x);
        float dy = __fsub_rn(cy, p.y);
        float dz = __fsub_rn(cz, p.z);
        float d2 = __fadd_rn(__fadd_rn(__fmul_rn(dx, dx), __fmul_rn(dy, dy)), __fmul_rn(dz, dz));
        key[j] = ((unsigned long long)__float_as_uint(d2) << 32) | (unsigned)i;
        tmin = umin64(tmin, key[j]);
    }

    // exact upper bound on the 32nd-smallest key:
    // per warp, max over the 32 lanes' thread-minima = max of 32 distinct keys
    // => >=32 keys <= it; block bound U = min over the 8 warps' bounds.
    unsigned long long wmax = tmin;
    #pragma unroll
    for (int o = 16; o; o >>= 1)
        wmax = umax64(wmax, __shfl_xor_sync(0xffffffffu, wmax, o));
    if (lane == 0) sU[tid >> 5] = wmax;
    __syncthreads();
    unsigned long long U = sU[0];
    #pragma unroll
    for (int w = 1; w < 8; w++) U = umin64(U, sU[w]);

    // pass 1: exponent-byte histogram, only for keys <= U (keys > U can't be top-32)
    #pragma unroll
    for (int j = 0; j < 16; j++) {
        if (key[j] <= U)
            atomicAdd(&hist[(unsigned)(key[j] >> 55)], 1);
    }
    __syncthreads();

    // warp 0: find exponent bin containing rank 32 (inclusive), count strictly below
    if (tid < 32) {
        int loc[8]; int s = 0;
        #pragma unroll
        for (int q = 0; q < 8; q++) { loc[q] = hist[lane * 8 + q]; s += loc[q]; }
        int incl = s;
        #pragma unroll
        for (int o = 1; o < 32; o <<= 1) {
            int v = __shfl_up_sync(0xffffffffu, incl, o);
            if (lane >= o) incl += v;
        }
        int excl = incl - s;
        unsigned bal = __ballot_sync(0xffffffffu, excl < NSAMPLE && NSAMPLE <= incl);
        if (lane == (int)(__ffs(bal) - 1)) {
            int c = excl;
            #pragma unroll
            for (int q = 0; q < 8; q++) {
                if (NSAMPLE <= c + loc[q]) { s_bin = lane * 8 + q; s_below = c; break; }
                c += loc[q];
            }
        }
    }
    __syncthreads();
    const int estar  = s_bin;
    const int below1 = s_below;
    if (tid < 256) hist[tid] = 0;
    __syncthreads();

    // pass 2: mantissa-byte histogram within exponent bin estar (unguarded: exact counts)
    #pragma unroll
    for (int j = 0; j < 16; j++) {
        unsigned hi = (unsigned)(key[j] >> 32);
        if ((int)(hi >> 23) == estar)
            atomicAdd(&hist[(hi >> 15) & 0xFF], 1);
    }
    __syncthreads();
    const int R2 = NSAMPLE - below1;
    if (tid < 32) {
        int loc[8]; int s = 0;
        #pragma unroll
        for (int q = 0; q < 8; q++) { loc[q] = hist[lane * 8 + q]; s += loc[q]; }
        int incl = s;
        #pragma unroll
        for (int o = 1; o < 32; o <<= 1) {
            int v = __shfl_up_sync(0xffffffffu, incl, o);
            if (lane >= o) incl += v;
        }
        int excl = incl - s;
        unsigned bal = __ballot_sync(0xffffffffu, excl < R2 && R2 <= incl);
        if (lane == (int)(__ffs(bal) - 1)) {
            int c = excl;
            #pragma unroll
            for (int q = 0; q < 8; q++) {
                if (R2 <= c + loc[q]) { s_bin = lane * 8 + q; s_below = c; break; }
                c += loc[q];
            }
        }
    }
    __syncthreads();
    const int mstar  = s_bin;
    const int below2 = s_below;
    const int r2     = R2 - below2;        // 1..32, picked from boundary slice

    // direct-select strict-below prefix; boundary slice -> candidate list.
    // Guard on <= U is exact: any key > U has (exp,mant) >= U's, so it can never be
    // strictly below (estar,mstar), and everything pickable from the boundary slice
    // is <= 32nd <= U, hence retained.
    #pragma unroll
    for (int j = 0; j < 16; j++) {
        if (key[j] > U) continue;
        unsigned hi = (unsigned)(key[j] >> 32);
        int e = hi >> 23, m = (hi >> 15) & 0xFF;
        if (e < estar || (e == estar && m < mstar)) {
            int p = atomicAdd(&s_nsel, 1);
            sel[p] = (int)(key[j] & 0xffffffffu);
        } else if (e == estar && m == mstar) {
            int p = atomicAdd(&s_ncand, 1);
            if (p < 512) cand[p] = key[j]; else s_ovf = 1;
        }
    }
    __syncthreads();

    // tiny tournament: r2 smallest of the candidate slice (typically 1-4 entries)
    if (tid < 32) {
        int C = s_ncand < 512 ? s_ncand : 512;
        (void)s_ovf;
        for (int t = 0; t < r2; t++) {
            unsigned long long best = ~0ULL;
            for (int i = lane; i < C; i += 32) best = umin64(best, cand[i]);
            #pragma unroll
            for (int o = 16; o; o >>= 1)
                best = umin64(best, __shfl_xor_sync(0xffffffffu, best, o));
            for (int i = lane; i < C; i += 32)
                if (cand[i] == best) {                  // keys unique: one lane hits
                    cand[i] = ~0ULL;
                    sel[NSAMPLE - r2 + t] = (int)(best & 0xffffffffu);
                }
        }
    }
    __syncthreads();

    if (tid < NSAMPLE) {
        int pi = sel[tid];
        g_idx[bn * NSAMPLE + tid] = pi;
        atomicAdd(&g_cnt[base + pi], 1);    // integer adds: deterministic
    }
}

// ---------------- TF32 GEMM on unique rows + weighted BN partials ----------------
template<int KTILES, bool AFF>
__global__ __launch_bounds__(256)
void gemm_tf32_kernel(const float* __restrict__ X, int ldx,
                      const float* __restrict__ W, int Kvalid,
                      const float* __restrict__ bias,
                      const float* __restrict__ scl,
                      const float* __restrict__ shf,
                      float* __restrict__ Y, int OC) {
    constexpr int KTOT = KTILES * 32;
    __shared__ uint32_t As[128][32];       // XOR-swizzled: col = k ^ ((row&7)<<2)
    __shared__ uint32_t Bs[64][KTOT];

    const int tid  = threadIdx.x;
    const int lane = tid & 31;
    const int wid  = tid >> 5;
    const int wm   = wid & 3;
    const int wn   = wid >> 2;
    const int m0   = blockIdx.y * 128;
    const int oc0  = blockIdx.x * 64;
    const int g    = lane >> 2;
    const int swz  = g << 2;

    for (int idx = tid; idx < 64 * KTOT; idx += 256) {
        int oc = idx / KTOT, k = idx - oc * KTOT;
        float wv = (k < Kvalid) ? W[(size_t)(oc0 + oc) * Kvalid + k] : 0.f;
        Bs[oc][k ^ ((oc & 7) << 2)] = cvt_tf32(wv);
    }

    float acc[2][4][4];
    #pragma unroll
    for (int i = 0; i < 2; i++)
        #pragma unroll
        for (int j = 0; j < 4; j++)
            #pragma unroll
            for (int k = 0; k < 4; k++) acc[i][j][k] = 0.f;

    float4 pf[4];
    auto lda = [&](int kt) {
        #pragma unroll
        for (int it = 0; it < 4; it++) {
            int idx = tid + it * 256;
            int row = idx >> 3, q = idx & 7;
            int kk  = kt * 32 + q * 4;
            pf[it] = make_float4(0.f, 0.f, 0.f, 0.f);
            if (kk < ldx)
                pf[it] = *reinterpret_cast<const float4*>(X + (size_t)(m0 + row) * ldx + kk);
        }
    };
    auto sta = [&](int kt) {
        #pragma unroll
        for (int it = 0; it < 4; it++) {
            int idx = tid + it * 256;
            int row = idx >> 3, q = idx & 7;
            int kk  = kt * 32 + q * 4;
            float4 v = pf[it];
            if (AFF && kk < ldx) {
                float4 s4 = *reinterpret_cast<const float4*>(scl + kk);
                float4 h4 = *reinterpret_cast<const float4*>(shf + kk);
                v.x = fmaxf(fmaf(v.x, s4.x, h4.x), 0.f);
                v.y = fmaxf(fmaf(v.y, s4.y, h4.y), 0.f);
                v.z = fmaxf(fmaf(v.z, s4.z, h4.z), 0.f);
                v.w = fmaxf(fmaf(v.w, s4.w, h4.w), 0.f);
            }
            uint4 u;
            u.x = cvt_tf32(v.x); u.y = cvt_tf32(v.y);
            u.z = cvt_tf32(v.z); u.w = cvt_tf32(v.w);
            *reinterpret_cast<uint4*>(&As[row][(q * 4) ^ ((row & 7) << 2)]) = u;
        }
    };

    lda(0); sta(0);
    __syncthreads();

    #pragma unroll
    for (int kt = 0; kt < KTILES; kt++) {
        if (kt + 1 < KTILES) lda(kt + 1);
        #pragma unroll
        for (int kc = 0; kc < 4; kc++) {
            const int k0 = kc * 8 + (lane & 3);
            uint32_t a[2][4];
            #pragma unroll
            for (int mi = 0; mi < 2; mi++) {
                int r = wm * 32 + mi * 16 + g;
                a[mi][0] = As[r][k0 ^ swz];
                a[mi][1] = As[r + 8][k0 ^ swz];
                a[mi][2] = As[r][(k0 + 4) ^ swz];
                a[mi][3] = As[r + 8][(k0 + 4) ^ swz];
            }
            uint32_t bb[4][2];
            #pragma unroll
            for (int ni = 0; ni < 4; ni++) {
                int c = wn * 32 + ni * 8 + g;
                int kb = kt * 32;
                bb[ni][0] = Bs[c][(kb + k0) ^ swz];
                bb[ni][1] = Bs[c][(kb + k0 + 4) ^ swz];
            }
            #pragma unroll
            for (int mi = 0; mi < 2; mi++)
                #pragma unroll
                for (int ni = 0; ni < 4; ni++)
                    mma_tf32(acc[mi][ni], a[mi], bb[ni]);
        }
        __syncthreads();
        if (kt + 1 < KTILES) {
            sta(kt + 1);
            __syncthreads();
        }
    }

    // ---- epilogue: +bias, store raw Y, count-weighted deterministic BN partials ----
    float (*sred)[4][64] = reinterpret_cast<float (*)[4][64]>(&As[0][0]);

    const int rbase = m0 + wm * 32 + g;
    float wgt[4];
    #pragma unroll
    for (int q = 0; q < 4; q++) wgt[q] = (float)g_cnt[rbase + q * 8];

    #pragma unroll
    for (int ni = 0; ni < 4; ni++) {
        int cl = wn * 32 + ni * 8 + 2 * (lane & 3);
        int c  = oc0 + cl;
        float b0 = bias[c], b1 = bias[c + 1];
        float s0 = 0.f, q0 = 0.f, s1 = 0.f, q1 = 0.f;
        #pragma unroll
        for (int mi = 0; mi < 2; mi++) {
            int r = m0 + wm * 32 + mi * 16 + g;
            float wA = wgt[mi * 2], wB = wgt[mi * 2 + 1];
            float v00 = acc[mi][ni][0] + b0;
            float v01 = acc[mi][ni][1] + b1;
            float v10 = acc[mi][ni][2] + b0;
            float v11 = acc[mi][ni][3] + b1;
            *reinterpret_cast<float2*>(Y + (size_t)r * OC + c)       = make_float2(v00, v01);
            *reinterpret_cast<float2*>(Y + (size_t)(r + 8) * OC + c) = make_float2(v10, v11);
            s0 += wA * v00 + wB * v10;  q0 += wA * v00 * v00 + wB * v10 * v10;
            s1 += wA * v01 + wB * v11;  q1 += wA * v01 * v01 + wB * v11 * v11;
        }
        #pragma unroll
        for (int o = 4; o < 32; o <<= 1) {
            s0 += __shfl_xor_sync(0xffffffffu, s0, o);
            q0 += __shfl_xor_sync(0xffffffffu, q0, o);
            s1 += __shfl_xor_sync(0xffffffffu, s1, o);
            q1 += __shfl_xor_sync(0xffffffffu, q1, o);
        }
        if (g == 0) {
            sred[0][wm][cl]     = s0;
            sred[1][wm][cl]     = q0;
            sred[0][wm][cl + 1] = s1;
            sred[1][wm][cl + 1] = q1;
        }
    }
    __syncthreads();
    if (tid < 128) {
        int part = tid >> 6, c = tid & 63;
        float s = sred[part][0][c] + sred[part][1][c] + sred[part][2][c] + sred[part][3][c];
        g_part[part][(size_t)(oc0 + c) * NSTATB + blockIdx.y] = s;
    }
}

// ---------------- stats stage 2: mean/var over gathered population ----------------
__global__ __launch_bounds__(256)
void stats_final_kernel(const float* __restrict__ gamma, const float* __restrict__ beta) {
    const int oc  = blockIdx.x;
    const int tid = threadIdx.x;
    float s = 0.f, s2 = 0.f;
    for (int i = tid; i < NSTATB; i += 256) {
        s  += g_part[0][(size_t)oc * NSTATB + i];
        s2 += g_part[1][(size_t)oc * NSTATB + i];
    }
    __shared__ float sh[2][256];
    sh[0][tid] = s; sh[1][tid] = s2;
    __syncthreads();
    for (int off = 128; off; off >>= 1) {
        if (tid < off) {
            sh[0][tid] += sh[0][tid + off];
            sh[1][tid] += sh[1][tid + off];
        }
        __syncthreads();
    }
    if (tid == 0) {
        float inv  = 1.0f / (float)M_TOTAL;
        float mean = sh[0][0] * inv;
        float var  = sh[1][0] * inv - mean * mean;
        float sc   = gamma[oc] / sqrtf(var + EPSV);
        g_scale[oc] = sc;
        g_shift[oc] = beta[oc] - mean * sc;
    }
}

// ---------------- final: gather Y2 rows, BN+ReLU, max over 32 samples ----------------
__global__ __launch_bounds__(256)
void maxpool_kernel(const float* __restrict__ Y2, float* __restrict__ outp) {
    __shared__ int sidx[NSAMPLE];
    const int bn  = blockIdx.x;
    const int b   = bn >> 10;
    const int tid = threadIdx.x;
    if (tid < NSAMPLE) sidx[tid] = g_idx[bn * NSAMPLE + tid];
    __syncthreads();
    const float sc = g_scale[tid], sh = g_shift[tid];
    float m = -3.4e38f;
    #pragma unroll
    for (int s = 0; s < NSAMPLE; s++) {
        size_t row = (size_t)(b * NPTS + sidx[s]);
        float v = fmaxf(fmaf(Y2[row * 256 + tid], sc, sh), 0.f);
        m = fmaxf(m, v);
    }
    outp[(size_t)bn * 256 + tid] = m;
}

// ---------------- launch ----------------
extern "C" void kernel_launch(void* const* d_in, const int* in_sizes, int n_in,
                              void* d_out, int out_size) {
    (void)in_sizes; (void)n_in; (void)out_size;
    const float* xyz = (const float*)d_in[0];
    const float* pts = (const float*)d_in[1];
    const int*   fps = (const int*)d_in[2];
    const float* w0  = (const float*)d_in[3];
    const float* b0  = (const float*)d_in[4];
    const float* gm0 = (const float*)d_in[5];
    const float* bt0 = (const float*)d_in[6];
    const float* w1  = (const float*)d_in[7];
    const float* b1  = (const float*)d_in[8];
    const float* gm1 = (const float*)d_in[9];
    const float* bt1 = (const float*)d_in[10];
    const float* w2  = (const float*)d_in[11];
    const float* b2  = (const float*)d_in[12];
    const float* gm2 = (const float*)d_in[13];
    const float* bt2 = (const float*)d_in[14];
    float* out = (float*)d_out;

    void *pX0, *pY0, *pY1, *pY2, *pSc, *pSh;
    cudaGetSymbolAddress(&pX0, g_X0);
    cudaGetSymbolAddress(&pY0, g_Y0);
    cudaGetSymbolAddress(&pY1, g_Y1);
    cudaGetSymbolAddress(&pY2, g_Y2);
    cudaGetSymbolAddress(&pSc, g_scale);
    cudaGetSymbolAddress(&pSh, g_shift);
    float* X0 = (float*)pX0;
    float* Y0 = (float*)pY0;
    float* Y1 = (float*)pY1;
    float* Y2 = (float*)pY2;
    const float* Sc = (const float*)pSc;
    const float* Sh = (const float*)pSh;

    prep_kernel<<<2048, 256>>>(xyz, pts);
    knn_kernel<<<BATCH * NPOINT, 256>>>(fps, out);

    gemm_tf32_kernel<3, false><<<dim3(1, MU / 128), 256>>>(
        X0, K0PAD, w0, 67, b0, nullptr, nullptr, Y0, 64);
    stats_final_kernel<<<64, 256>>>(gm0, bt0);

    gemm_tf32_kernel<2, true><<<dim3(2, MU / 128), 256>>>(
        Y0, 64, w1, 64, b1, Sc, Sh, Y1, 128);
    stats_final_kernel<<<128, 256>>>(gm1, bt1);

    gemm_tf32_kernel<4, true><<<dim3(4, MU / 128), 256>>>(
        Y1, 128, w2, 128, b2, Sc, Sh, Y2, 256);
    stats_final_kernel<<<256, 256>>>(gm2, bt2);

    maxpool_kernel<<<BATCH * NPOINT, 256>>>(Y2, out + NEWXYZ);
}

// round 11
// speedup vs baseline: 1.0684x; 1.0172x over previous
#include <cuda_runtime.h>
#include <cstdint>
#include <cstddef>

#define BATCH   8
#define NPTS    4096
#define NPOINT  1024
#define NSAMPLE 32
#define CFEAT   64
#define K0PAD   72
#define EPSV    1e-5f

constexpr int M_TOTAL = BATCH * NPOINT * NSAMPLE;   // 262144 (BN population)
constexpr int MU      = BATCH * NPTS;               // 32768 unique rows
constexpr int NEWXYZ  = BATCH * NPOINT * 3;         // 24576
constexpr int NSTATB  = MU / 128;                   // 256 partial blocks (= gemm grid.y)

// ---------------- device scratch ----------------
__device__ float g_X0[(size_t)MU * K0PAD];
__device__ float g_Y0[(size_t)MU * 64];
__device__ float g_Y1[(size_t)MU * 128];
__device__ float g_Y2[(size_t)MU * 256];
__device__ int   g_cnt[MU];                         // occurrence histogram
__device__ int   g_idx[BATCH * NPOINT * NSAMPLE];   // selected neighbor ids (set, any order)
__device__ float g_part[2][256 * NSTATB];
__device__ float g_scale[256];
__device__ float g_shift[256];

// ---------------- helpers ----------------
__device__ __forceinline__ uint32_t cvt_tf32(float x) {
    uint32_t r; asm("cvt.rna.tf32.f32 %0, %1;" : "=r"(r) : "f"(x)); return r;
}
__device__ __forceinline__ void mma_tf32(float d[4], const uint32_t a[4], const uint32_t b[2]) {
    asm volatile("mma.sync.aligned.m16n8k8.row.col.f32.tf32.tf32.f32 "
                 "{%0,%1,%2,%3}, {%4,%5,%6,%7}, {%8,%9}, {%0,%1,%2,%3};"
                 : "+f"(d[0]), "+f"(d[1]), "+f"(d[2]), "+f"(d[3])
                 : "r"(a[0]), "r"(a[1]), "r"(a[2]), "r"(a[3]),
                   "r"(b[0]), "r"(b[1]));
}
__device__ __forceinline__ unsigned long long umin64(unsigned long long a, unsigned long long b) {
    return a < b ? a : b;
}
__device__ __forceinline__ unsigned long long umax64(unsigned long long a, unsigned long long b) {
    return a > b ? a : b;
}

// ---------------- prep: zero histogram + build unique-row input X0 ----------------
__global__ __launch_bounds__(256)
void prep_kernel(const float* __restrict__ xyz, const float* __restrict__ pts) {
    const int stride = gridDim.x * blockDim.x;
    int i = blockIdx.x * blockDim.x + threadIdx.x;
    if (i < MU) g_cnt[i] = 0;
    for (int e = i; e < MU * K0PAD; e += stride) {
        int r = e / K0PAD, c = e - r * K0PAD;     // r = b*NPTS + pi
        float v = 0.f;
        if (c < 3)              v = xyz[(size_t)r * 3 + c];
        else if (c < 3 + CFEAT) v = pts[(size_t)r * CFEAT + (c - 3)];
        g_X0[e] = v;
    }
}

// ---------------- KNN via exact 2-level radix select + U-bound prefilter ----------------
// Finds the 32 smallest unique keys (d2_bits<<32|idx). Output order irrelevant.
__global__ __launch_bounds__(256)
void knn_kernel(const float* __restrict__ xyz,
                const int*   __restrict__ fps,
                float*       __restrict__ out_newxyz) {
    __shared__ int hist[256];
    __shared__ unsigned long long cand[512];
    __shared__ unsigned long long sU[8];
    __shared__ int sel[NSAMPLE];
    __shared__ int s_bin, s_below;      // reused for both passes
    __shared__ int s_nsel, s_ncand, s_ovf;

    const int bn   = blockIdx.x;
    const int b    = bn >> 10;
    const int tid  = threadIdx.x;
    const int lane = tid & 31;
    const float* xb = xyz + (size_t)b * NPTS * 3;
    const int fi = fps[bn];
    const float cx = xb[fi * 3 + 0];
    const float cy = xb[fi * 3 + 1];
    const float cz = xb[fi * 3 + 2];
    if (tid == 0) {
        out_newxyz[bn * 3 + 0] = cx;
        out_newxyz[bn * 3 + 1] = cy;
        out_newxyz[bn * 3 + 2] = cz;
        s_nsel = 0; s_ncand = 0; s_ovf = 0;
    }
    if (tid < 256) hist[tid] = 0;
    __syncthreads();

    // keys in registers; d2 arithmetic order matches reference exactly
    unsigned long long key[16];
    unsigned long long tmin = ~0ULL;
    #pragma unroll
    for (int j = 0; j < 16; j++) {
        int i = tid + j * 256;
        float dx = __fsub_rn(cx, xb[i * 3 + 0]);
        float dy = __fsub_rn(cy, xb[i * 3 + 1]);
        float dz = __fsub_rn(cz, xb[i * 3 + 2]);
        float d2 = __fadd_rn(__fadd_rn(__fmul_rn(dx, dx), __fmul_rn(dy, dy)), __fmul_rn(dz, dz));
        key[j] = ((unsigned long long)__float_as_uint(d2) << 32) | (unsigned)i;
        tmin = umin64(tmin, key[j]);
    }

    // exact upper bound U on the 32nd-smallest key: per warp, the max over the
    // 32 lanes' thread-minima is the max of 32 distinct keys => >=32 keys <= it;
    // block bound U = min over the 8 warps' bounds.
    unsigned long long wmax = tmin;
    #pragma unroll
    for (int o = 16; o; o >>= 1)
        wmax = umax64(wmax, __shfl_xor_sync(0xffffffffu, wmax, o));
    if (lane == 0) sU[tid >> 5] = wmax;
    __syncthreads();
    unsigned long long U = sU[0];
    #pragma unroll
    for (int w = 1; w < 8; w++) U = umin64(U, sU[w]);

    // pass 1: exponent-byte histogram, only for keys <= U (keys > U can't be top-32;
    // bins at/below the rank-32 bin keep exact counts, so estar/below1 are unchanged)
    #pragma unroll
    for (int j = 0; j < 16; j++) {
        if (key[j] <= U)
            atomicAdd(&hist[(unsigned)(key[j] >> 55)], 1);
    }
    __syncthreads();

    // warp 0: find exponent bin containing rank 32 (inclusive), count strictly below
    if (tid < 32) {
        int loc[8]; int s = 0;
        #pragma unroll
        for (int q = 0; q < 8; q++) { loc[q] = hist[lane * 8 + q]; s += loc[q]; }
        int incl = s;
        #pragma unroll
        for (int o = 1; o < 32; o <<= 1) {
            int v = __shfl_up_sync(0xffffffffu, incl, o);
            if (lane >= o) incl += v;
        }
        int excl = incl - s;
        unsigned bal = __ballot_sync(0xffffffffu, excl < NSAMPLE && NSAMPLE <= incl);
        if (lane == (int)(__ffs(bal) - 1)) {
            int c = excl;
            #pragma unroll
            for (int q = 0; q < 8; q++) {
                if (NSAMPLE <= c + loc[q]) { s_bin = lane * 8 + q; s_below = c; break; }
                c += loc[q];
            }
        }
    }
    __syncthreads();
    const int estar  = s_bin;
    const int below1 = s_below;
    if (tid < 256) hist[tid] = 0;
    __syncthreads();

    // pass 2: mantissa-byte histogram within exponent bin estar (exact counts)
    #pragma unroll
    for (int j = 0; j < 16; j++) {
        unsigned hi = (unsigned)(key[j] >> 32);
        if ((int)(hi >> 23) == estar)
            atomicAdd(&hist[(hi >> 15) & 0xFF], 1);
    }
    __syncthreads();
    const int R2 = NSAMPLE - below1;
    if (tid < 32) {
        int loc[8]; int s = 0;
        #pragma unroll
        for (int q = 0; q < 8; q++) { loc[q] = hist[lane * 8 + q]; s += loc[q]; }
        int incl = s;
        #pragma unroll
        for (int o = 1; o < 32; o <<= 1) {
            int v = __shfl_up_sync(0xffffffffu, incl, o);
            if (lane >= o) incl += v;
        }
        int excl = incl - s;
        unsigned bal = __ballot_sync(0xffffffffu, excl < R2 && R2 <= incl);
        if (lane == (int)(__ffs(bal) - 1)) {
            int c = excl;
            #pragma unroll
            for (int q = 0; q < 8; q++) {
                if (R2 <= c + loc[q]) { s_bin = lane * 8 + q; s_below = c; break; }
                c += loc[q];
            }
        }
    }
    __syncthreads();
    const int mstar  = s_bin;
    const int below2 = s_below;
    const int r2     = R2 - below2;        // 1..32, picked from boundary slice

    // direct-select strict-below prefix; boundary slice -> candidate list.
    // <=U guard is exact: keys > U can't be strictly below (estar,mstar), and all
    // pickable boundary candidates are <= 32nd <= U.
    #pragma unroll
    for (int j = 0; j < 16; j++) {
        if (key[j] > U) continue;
        unsigned hi = (unsigned)(key[j] >> 32);
        int e = hi >> 23, m = (hi >> 15) & 0xFF;
        if (e < estar || (e == estar && m < mstar)) {
            int p = atomicAdd(&s_nsel, 1);
            sel[p] = (int)(key[j] & 0xffffffffu);
        } else if (e == estar && m == mstar) {
            int p = atomicAdd(&s_ncand, 1);
            if (p < 512) cand[p] = key[j]; else s_ovf = 1;
        }
    }
    __syncthreads();

    // tiny tournament: r2 smallest of the candidate slice (typically 1-4 entries)
    if (tid < 32) {
        int C = s_ncand < 512 ? s_ncand : 512;
        (void)s_ovf;
        for (int t = 0; t < r2; t++) {
            unsigned long long best = ~0ULL;
            for (int i = lane; i < C; i += 32) best = umin64(best, cand[i]);
            #pragma unroll
            for (int o = 16; o; o >>= 1)
                best = umin64(best, __shfl_xor_sync(0xffffffffu, best, o));
            for (int i = lane; i < C; i += 32)
                if (cand[i] == best) {                  // keys unique: one lane hits
                    cand[i] = ~0ULL;
                    sel[NSAMPLE - r2 + t] = (int)(best & 0xffffffffu);
                }
        }
    }
    __syncthreads();

    if (tid < NSAMPLE) {
        int pi = sel[tid];
        g_idx[bn * NSAMPLE + tid] = pi;
        atomicAdd(&g_cnt[b * NPTS + pi], 1);    // integer adds: deterministic
    }
}

// ---------------- TF32 GEMM on unique rows + weighted BN partials ----------------
template<int KTILES, bool AFF>
__global__ __launch_bounds__(256)
void gemm_tf32_kernel(const float* __restrict__ X, int ldx,
                      const float* __restrict__ W, int Kvalid,
                      const float* __restrict__ bias,
                      const float* __restrict__ scl,
                      const float* __restrict__ shf,
                      float* __restrict__ Y, int OC) {
    constexpr int KTOT = KTILES * 32;
    __shared__ uint32_t As[128][32];       // XOR-swizzled: col = k ^ ((row&7)<<2)
    __shared__ uint32_t Bs[64][KTOT];

    const int tid  = threadIdx.x;
    const int lane = tid & 31;
    const int wid  = tid >> 5;
    const int wm   = wid & 3;
    const int wn   = wid >> 2;
    const int m0   = blockIdx.y * 128;
    const int oc0  = blockIdx.x * 64;
    const int g    = lane >> 2;
    const int swz  = g << 2;

    for (int idx = tid; idx < 64 * KTOT; idx += 256) {
        int oc = idx / KTOT, k = idx - oc * KTOT;
        float wv = (k < Kvalid) ? W[(size_t)(oc0 + oc) * Kvalid + k] : 0.f;
        Bs[oc][k ^ ((oc & 7) << 2)] = cvt_tf32(wv);
    }

    float acc[2][4][4];
    #pragma unroll
    for (int i = 0; i < 2; i++)
        #pragma unroll
        for (int j = 0; j < 4; j++)
            #pragma unroll
            for (int k = 0; k < 4; k++) acc[i][j][k] = 0.f;

    float4 pf[4];
    auto lda = [&](int kt) {
        #pragma unroll
        for (int it = 0; it < 4; it++) {
            int idx = tid + it * 256;
            int row = idx >> 3, q = idx & 7;
            int kk  = kt * 32 + q * 4;
            pf[it] = make_float4(0.f, 0.f, 0.f, 0.f);
            if (kk < ldx)
                pf[it] = *reinterpret_cast<const float4*>(X + (size_t)(m0 + row) * ldx + kk);
        }
    };
    auto sta = [&](int kt) {
        #pragma unroll
        for (int it = 0; it < 4; it++) {
            int idx = tid + it * 256;
            int row = idx >> 3, q = idx & 7;
            int kk  = kt * 32 + q * 4;
            float4 v = pf[it];
            if (AFF && kk < ldx) {
                float4 s4 = *reinterpret_cast<const float4*>(scl + kk);
                float4 h4 = *reinterpret_cast<const float4*>(shf + kk);
                v.x = fmaxf(fmaf(v.x, s4.x, h4.x), 0.f);
                v.y = fmaxf(fmaf(v.y, s4.y, h4.y), 0.f);
                v.z = fmaxf(fmaf(v.z, s4.z, h4.z), 0.f);
                v.w = fmaxf(fmaf(v.w, s4.w, h4.w), 0.f);
            }
            uint4 u;
            u.x = cvt_tf32(v.x); u.y = cvt_tf32(v.y);
            u.z = cvt_tf32(v.z); u.w = cvt_tf32(v.w);
            *reinterpret_cast<uint4*>(&As[row][(q * 4) ^ ((row & 7) << 2)]) = u;
        }
    };

    lda(0); sta(0);
    __syncthreads();

    #pragma unroll
    for (int kt = 0; kt < KTILES; kt++) {
        if (kt + 1 < KTILES) lda(kt + 1);
        #pragma unroll
        for (int kc = 0; kc < 4; kc++) {
            const int k0 = kc * 8 + (lane & 3);
            uint32_t a[2][4];
            #pragma unroll
            for (int mi = 0; mi < 2; mi++) {
                int r = wm * 32 + mi * 16 + g;
                a[mi][0] = As[r][k0 ^ swz];
                a[mi][1] = As[r + 8][k0 ^ swz];
                a[mi][2] = As[r][(k0 + 4) ^ swz];
                a[mi][3] = As[r + 8][(k0 + 4) ^ swz];
            }
            uint32_t bb[4][2];
            #pragma unroll
            for (int ni = 0; ni < 4; ni++) {
                int c = wn * 32 + ni * 8 + g;
                int kb = kt * 32;
                bb[ni][0] = Bs[c][(kb + k0) ^ swz];
                bb[ni][1] = Bs[c][(kb + k0 + 4) ^ swz];
            }
            #pragma unroll
            for (int mi = 0; mi < 2; mi++)
                #pragma unroll
                for (int ni = 0; ni < 4; ni++)
                    mma_tf32(acc[mi][ni], a[mi], bb[ni]);
        }
        __syncthreads();
        if (kt + 1 < KTILES) {
            sta(kt + 1);
            __syncthreads();
        }
    }

    // ---- epilogue: +bias, store raw Y, count-weighted deterministic BN partials ----
    float (*sred)[4][64] = reinterpret_cast<float (*)[4][64]>(&As[0][0]);

    const int rbase = m0 + wm * 32 + g;
    float wgt[4];
    #pragma unroll
    for (int q = 0; q < 4; q++) wgt[q] = (float)g_cnt[rbase + q * 8];

    #pragma unroll
    for (int ni = 0; ni < 4; ni++) {
        int cl = wn * 32 + ni * 8 + 2 * (lane & 3);
        int c  = oc0 + cl;
        float b0 = bias[c], b1 = bias[c + 1];
        float s0 = 0.f, q0 = 0.f, s1 = 0.f, q1 = 0.f;
        #pragma unroll
        for (int mi = 0; mi < 2; mi++) {
            int r = m0 + wm * 32 + mi * 16 + g;
            float wA = wgt[mi * 2], wB = wgt[mi * 2 + 1];
            float v00 = acc[mi][ni][0] + b0;
            float v01 = acc[mi][ni][1] + b1;
            float v10 = acc[mi][ni][2] + b0;
            float v11 = acc[mi][ni][3] + b1;
            *reinterpret_cast<float2*>(Y + (size_t)r * OC + c)       = make_float2(v00, v01);
            *reinterpret_cast<float2*>(Y + (size_t)(r + 8) * OC + c) = make_float2(v10, v11);
            s0 += wA * v00 + wB * v10;  q0 += wA * v00 * v00 + wB * v10 * v10;
            s1 += wA * v01 + wB * v11;  q1 += wA * v01 * v01 + wB * v11 * v11;
        }
        #pragma unroll
        for (int o = 4; o < 32; o <<= 1) {
            s0 += __shfl_xor_sync(0xffffffffu, s0, o);
            q0 += __shfl_xor_sync(0xffffffffu, q0, o);
            s1 += __shfl_xor_sync(0xffffffffu, s1, o);
            q1 += __shfl_xor_sync(0xffffffffu, q1, o);
        }
        if (g == 0) {
            sred[0][wm][cl]     = s0;
            sred[1][wm][cl]     = q0;
            sred[0][wm][cl + 1] = s1;
            sred[1][wm][cl + 1] = q1;
        }
    }
    __syncthreads();
    if (tid < 128) {
        int part = tid >> 6, c = tid & 63;
        float s = sred[part][0][c] + sred[part][1][c] + sred[part][2][c] + sred[part][3][c];
        g_part[part][(size_t)(oc0 + c) * NSTATB + blockIdx.y] = s;
    }
}

// ---------------- stats stage 2: mean/var over gathered population ----------------
__global__ __launch_bounds__(256)
void stats_final_kernel(const float* __restrict__ gamma, const float* __restrict__ beta) {
    const int oc  = blockIdx.x;
    const int tid = threadIdx.x;
    float s = 0.f, s2 = 0.f;
    for (int i = tid; i < NSTATB; i += 256) {
        s  += g_part[0][(size_t)oc * NSTATB + i];
        s2 += g_part[1][(size_t)oc * NSTATB + i];
    }
    __shared__ float sh[2][256];
    sh[0][tid] = s; sh[1][tid] = s2;
    __syncthreads();
    for (int off = 128; off; off >>= 1) {
        if (tid < off) {
            sh[0][tid] += sh[0][tid + off];
            sh[1][tid] += sh[1][tid + off];
        }
        __syncthreads();
    }
    if (tid == 0) {
        float inv  = 1.0f / (float)M_TOTAL;
        float mean = sh[0][0] * inv;
        float var  = sh[1][0] * inv - mean * mean;
        float sc   = gamma[oc] / sqrtf(var + EPSV);
        g_scale[oc] = sc;
        g_shift[oc] = beta[oc] - mean * sc;
    }
}

// ---------------- final: gather Y2 rows, BN+ReLU, max over 32 samples ----------------
__global__ __launch_bounds__(256)
void maxpool_kernel(const float* __restrict__ Y2, float* __restrict__ outp) {
    __shared__ int sidx[NSAMPLE];
    const int bn  = blockIdx.x;
    const int b   = bn >> 10;
    const int tid = threadIdx.x;
    if (tid < NSAMPLE) sidx[tid] = g_idx[bn * NSAMPLE + tid];
    __syncthreads();
    const float sc = g_scale[tid], sh = g_shift[tid];
    float m = -3.4e38f;
    #pragma unroll
    for (int s = 0; s < NSAMPLE; s++) {
        size_t row = (size_t)(b * NPTS + sidx[s]);
        float v = fmaxf(fmaf(Y2[row * 256 + tid], sc, sh), 0.f);
        m = fmaxf(m, v);
    }
    outp[(size_t)bn * 256 + tid] = m;
}

// ---------------- launch ----------------
extern "C" void kernel_launch(void* const* d_in, const int* in_sizes, int n_in,
                              void* d_out, int out_size) {
    (void)in_sizes; (void)n_in; (void)out_size;
    const float* xyz = (const float*)d_in[0];
    const float* pts = (const float*)d_in[1];
    const int*   fps = (const int*)d_in[2];
    const float* w0  = (const float*)d_in[3];
    const float* b0  = (const float*)d_in[4];
    const float* gm0 = (const float*)d_in[5];
    const float* bt0 = (const float*)d_in[6];
    const float* w1  = (const float*)d_in[7];
    const float* b1  = (const float*)d_in[8];
    const float* gm1 = (const float*)d_in[9];
    const float* bt1 = (const float*)d_in[10];
    const float* w2  = (const float*)d_in[11];
    const float* b2  = (const float*)d_in[12];
    const float* gm2 = (const float*)d_in[13];
    const float* bt2 = (const float*)d_in[14];
    float* out = (float*)d_out;

    void *pX0, *pY0, *pY1, *pY2, *pSc, *pSh;
    cudaGetSymbolAddress(&pX0, g_X0);
    cudaGetSymbolAddress(&pY0, g_Y0);
    cudaGetSymbolAddress(&pY1, g_Y1);
    cudaGetSymbolAddress(&pY2, g_Y2);
    cudaGetSymbolAddress(&pSc, g_scale);
    cudaGetSymbolAddress(&pSh, g_shift);
    float* X0 = (float*)pX0;
    float* Y0 = (float*)pY0;
    float* Y1 = (float*)pY1;
    float* Y2 = (float*)pY2;
    const float* Sc = (const float*)pSc;
    const float* Sh = (const float*)pSh;

    prep_kernel<<<2048, 256>>>(xyz, pts);
    knn_kernel<<<BATCH * NPOINT, 256>>>(xyz, fps, out);

    gemm_tf32_kernel<3, false><<<dim3(1, MU / 128), 256>>>(
        X0, K0PAD, w0, 67, b0, nullptr, nullptr, Y0, 64);
    stats_final_kernel<<<64, 256>>>(gm0, bt0);

    gemm_tf32_kernel<2, true><<<dim3(2, MU / 128), 256>>>(
        Y0, 64, w1, 64, b1, Sc, Sh, Y1, 128);
    stats_final_kernel<<<128, 256>>>(gm1, bt1);

    gemm_tf32_kernel<4, true><<<dim3(4, MU / 128), 256>>>(
        Y1, 128, w2, 128, b2, Sc, Sh, Y2, 256);
    stats_final_kernel<<<256, 256>>>(gm2, bt2);

    maxpool_kernel<<<BATCH * NPOINT, 256>>>(Y2, out + NEWXYZ);
}

// round 12
// speedup vs baseline: 1.2755x; 1.1939x over previous
#include <cuda_runtime.h>
#include <cstdint>
#include <cstddef>

#define BATCH   8
#define NPTS    4096
#define NPOINT  1024
#define NSAMPLE 32
#define CFEAT   64
#define K0PAD   72
#define EPSV    1e-5f

constexpr int M_TOTAL = BATCH * NPOINT * NSAMPLE;   // 262144 (BN population)
constexpr int MU      = BATCH * NPTS;               // 32768 unique rows
constexpr int NEWXYZ  = BATCH * NPOINT * 3;         // 24576
constexpr int NSTATB  = MU / 128;                   // 256 partial blocks (= gemm grid.y)

// ---------------- device scratch ----------------
__device__ float g_X0[(size_t)MU * K0PAD];
__device__ float g_Y0[(size_t)MU * 64];
__device__ float g_Y1[(size_t)MU * 128];
__device__ float g_Y2[(size_t)MU * 256];
__device__ int   g_cnt[MU];                         // occurrence histogram
__device__ int   g_idx[BATCH * NPOINT * NSAMPLE];   // selected neighbor ids (set, any order)
__device__ float g_part[2][256 * NSTATB];
__device__ float g_scale[256];
__device__ float g_shift[256];

// ---------------- helpers ----------------
__device__ __forceinline__ uint32_t cvt_tf32(float x) {
    uint32_t r; asm("cvt.rna.tf32.f32 %0, %1;" : "=r"(r) : "f"(x)); return r;
}
__device__ __forceinline__ void mma_tf32(float d[4], const uint32_t a[4], const uint32_t b[2]) {
    asm volatile("mma.sync.aligned.m16n8k8.row.col.f32.tf32.tf32.f32 "
                 "{%0,%1,%2,%3}, {%4,%5,%6,%7}, {%8,%9}, {%0,%1,%2,%3};"
                 : "+f"(d[0]), "+f"(d[1]), "+f"(d[2]), "+f"(d[3])
                 : "r"(a[0]), "r"(a[1]), "r"(a[2]), "r"(a[3]),
                   "r"(b[0]), "r"(b[1]));
}
__device__ __forceinline__ unsigned long long umin64(unsigned long long a, unsigned long long b) {
    return a < b ? a : b;
}

// ---------------- prep: zero histogram + build unique-row input X0 ----------------
__global__ __launch_bounds__(256)
void prep_kernel(const float* __restrict__ xyz, const float* __restrict__ pts) {
    const int stride = gridDim.x * blockDim.x;
    int i = blockIdx.x * blockDim.x + threadIdx.x;
    if (i < MU) g_cnt[i] = 0;
    for (int e = i; e < MU * K0PAD; e += stride) {
        int r = e / K0PAD, c = e - r * K0PAD;     // r = b*NPTS + pi
        float v = 0.f;
        if (c < 3)              v = xyz[(size_t)r * 3 + c];
        else if (c < 3 + CFEAT) v = pts[(size_t)r * CFEAT + (c - 3)];
        g_X0[e] = v;
    }
}

// ---------------- KNN via exact 2-level radix select (R7-identical) ----------------
__global__ __launch_bounds__(256)
void knn_kernel(const float* __restrict__ xyz,
                const int*   __restrict__ fps,
                float*       __restrict__ out_newxyz) {
    __shared__ int hist[256];
    __shared__ unsigned long long cand[512];
    __shared__ int sel[NSAMPLE];
    __shared__ int s_bin, s_below;      // reused for both passes
    __shared__ int s_nsel, s_ncand, s_ovf;

    const int bn   = blockIdx.x;
    const int b    = bn >> 10;
    const int tid  = threadIdx.x;
    const int lane = tid & 31;
    const float* xb = xyz + (size_t)b * NPTS * 3;
    const int fi = fps[bn];
    const float cx = xb[fi * 3 + 0];
    const float cy = xb[fi * 3 + 1];
    const float cz = xb[fi * 3 + 2];
    if (tid == 0) {
        out_newxyz[bn * 3 + 0] = cx;
        out_newxyz[bn * 3 + 1] = cy;
        out_newxyz[bn * 3 + 2] = cz;
        s_nsel = 0; s_ncand = 0; s_ovf = 0;
    }
    if (tid < 256) hist[tid] = 0;
    __syncthreads();

    // keys in registers; d2 arithmetic order matches reference exactly
    unsigned long long key[16];
    #pragma unroll
    for (int j = 0; j < 16; j++) {
        int i = tid + j * 256;
        float dx = __fsub_rn(cx, xb[i * 3 + 0]);
        float dy = __fsub_rn(cy, xb[i * 3 + 1]);
        float dz = __fsub_rn(cz, xb[i * 3 + 2]);
        float d2 = __fadd_rn(__fadd_rn(__fmul_rn(dx, dx), __fmul_rn(dy, dy)), __fmul_rn(dz, dz));
        key[j] = ((unsigned long long)__float_as_uint(d2) << 32) | (unsigned)i;
        atomicAdd(&hist[(unsigned)(key[j] >> 55)], 1);          // exponent byte
    }
    __syncthreads();

    // warp 0: find exponent bin containing rank 32 (inclusive), count strictly below
    if (tid < 32) {
        int loc[8]; int s = 0;
        #pragma unroll
        for (int q = 0; q < 8; q++) { loc[q] = hist[lane * 8 + q]; s += loc[q]; }
        int incl = s;
        #pragma unroll
        for (int o = 1; o < 32; o <<= 1) {
            int v = __shfl_up_sync(0xffffffffu, incl, o);
            if (lane >= o) incl += v;
        }
        int excl = incl - s;
        unsigned bal = __ballot_sync(0xffffffffu, excl < NSAMPLE && NSAMPLE <= incl);
        if (lane == (int)(__ffs(bal) - 1)) {
            int c = excl;
            #pragma unroll
            for (int q = 0; q < 8; q++) {
                if (NSAMPLE <= c + loc[q]) { s_bin = lane * 8 + q; s_below = c; break; }
                c += loc[q];
            }
        }
    }
    __syncthreads();
    const int estar  = s_bin;
    const int below1 = s_below;
    if (tid < 256) hist[tid] = 0;
    __syncthreads();

    // pass 2: mantissa-byte histogram within exponent bin estar
    #pragma unroll
    for (int j = 0; j < 16; j++) {
        unsigned hi = (unsigned)(key[j] >> 32);
        if ((int)(hi >> 23) == estar)
            atomicAdd(&hist[(hi >> 15) & 0xFF], 1);
    }
    __syncthreads();
    const int R2 = NSAMPLE - below1;
    if (tid < 32) {
        int loc[8]; int s = 0;
        #pragma unroll
        for (int q = 0; q < 8; q++) { loc[q] = hist[lane * 8 + q]; s += loc[q]; }
        int incl = s;
        #pragma unroll
        for (int o = 1; o < 32; o <<= 1) {
            int v = __shfl_up_sync(0xffffffffu, incl, o);
            if (lane >= o) incl += v;
        }
        int excl = incl - s;
        unsigned bal = __ballot_sync(0xffffffffu, excl < R2 && R2 <= incl);
        if (lane == (int)(__ffs(bal) - 1)) {
            int c = excl;
            #pragma unroll
            for (int q = 0; q < 8; q++) {
                if (R2 <= c + loc[q]) { s_bin = lane * 8 + q; s_below = c; break; }
                c += loc[q];
            }
        }
    }
    __syncthreads();
    const int mstar  = s_bin;
    const int below2 = s_below;
    const int r2     = R2 - below2;        // 1..32, picked from boundary slice

    // direct-select strict-below prefix; boundary slice -> candidate list
    #pragma unroll
    for (int j = 0; j < 16; j++) {
        unsigned hi = (unsigned)(key[j] >> 32);
        int e = hi >> 23, m = (hi >> 15) & 0xFF;
        if (e < estar || (e == estar && m < mstar)) {
            int p = atomicAdd(&s_nsel, 1);
            sel[p] = (int)(key[j] & 0xffffffffu);
        } else if (e == estar && m == mstar) {
            int p = atomicAdd(&s_ncand, 1);
            if (p < 512) cand[p] = key[j]; else s_ovf = 1;
        }
    }
    __syncthreads();

    // tiny tournament: r2 smallest of the candidate slice (typically 1-4 entries)
    if (tid < 32) {
        int C = s_ncand < 512 ? s_ncand : 512;
        (void)s_ovf;
        for (int t = 0; t < r2; t++) {
            unsigned long long best = ~0ULL;
            for (int i = lane; i < C; i += 32) best = umin64(best, cand[i]);
            #pragma unroll
            for (int o = 16; o; o >>= 1)
                best = umin64(best, __shfl_xor_sync(0xffffffffu, best, o));
            for (int i = lane; i < C; i += 32)
                if (cand[i] == best) {                  // keys unique: one lane hits
                    cand[i] = ~0ULL;
                    sel[NSAMPLE - r2 + t] = (int)(best & 0xffffffffu);
                }
        }
    }
    __syncthreads();

    if (tid < NSAMPLE) {
        int pi = sel[tid];
        g_idx[bn * NSAMPLE + tid] = pi;
        atomicAdd(&g_cnt[b * NPTS + pi], 1);    // integer adds: deterministic
    }
}

// ---------------- TF32 GEMM: register-pipelined fragments ----------------
template<int KTILES, bool AFF>
__global__ __launch_bounds__(256, 2)
void gemm_tf32_kernel(const float* __restrict__ X, int ldx,
                      const float* __restrict__ W, int Kvalid,
                      const float* __restrict__ bias,
                      const float* __restrict__ scl,
                      const float* __restrict__ shf,
                      float* __restrict__ Y, int OC) {
    constexpr int KTOT = KTILES * 32;
    __shared__ uint32_t As[128][32];       // XOR-swizzled: col = k ^ ((row&7)<<2)
    __shared__ uint32_t Bs[64][KTOT];

    const int tid  = threadIdx.x;
    const int lane = tid & 31;
    const int wid  = tid >> 5;
    const int wm   = wid & 3;
    const int wn   = wid >> 2;
    const int m0   = blockIdx.y * 128;
    const int oc0  = blockIdx.x * 64;
    const int g    = lane >> 2;
    const int swz  = g << 2;

    for (int idx = tid; idx < 64 * KTOT; idx += 256) {
        int oc = idx / KTOT, k = idx - oc * KTOT;
        float wv = (k < Kvalid) ? W[(size_t)(oc0 + oc) * Kvalid + k] : 0.f;
        Bs[oc][k ^ ((oc & 7) << 2)] = cvt_tf32(wv);
    }

    float acc[2][4][4];
    #pragma unroll
    for (int i = 0; i < 2; i++)
        #pragma unroll
        for (int j = 0; j < 4; j++)
            #pragma unroll
            for (int k = 0; k < 4; k++) acc[i][j][k] = 0.f;

    float4 pf[4];
    auto lda = [&](int kt) {
        #pragma unroll
        for (int it = 0; it < 4; it++) {
            int idx = tid + it * 256;
            int row = idx >> 3, q = idx & 7;
            int kk  = kt * 32 + q * 4;
            pf[it] = make_float4(0.f, 0.f, 0.f, 0.f);
            if (kk < ldx)
                pf[it] = *reinterpret_cast<const float4*>(X + (size_t)(m0 + row) * ldx + kk);
        }
    };
    auto sta = [&](int kt) {
        #pragma unroll
        for (int it = 0; it < 4; it++) {
            int idx = tid + it * 256;
            int row = idx >> 3, q = idx & 7;
            int kk  = kt * 32 + q * 4;
            float4 v = pf[it];
            if (AFF && kk < ldx) {
                float4 s4 = *reinterpret_cast<const float4*>(scl + kk);
                float4 h4 = *reinterpret_cast<const float4*>(shf + kk);
                v.x = fmaxf(fmaf(v.x, s4.x, h4.x), 0.f);
                v.y = fmaxf(fmaf(v.y, s4.y, h4.y), 0.f);
                v.z = fmaxf(fmaf(v.z, s4.z, h4.z), 0.f);
                v.w = fmaxf(fmaf(v.w, s4.w, h4.w), 0.f);
            }
            uint4 u;
            u.x = cvt_tf32(v.x); u.y = cvt_tf32(v.y);
            u.z = cvt_tf32(v.z); u.w = cvt_tf32(v.w);
            *reinterpret_cast<uint4*>(&As[row][(q * 4) ^ ((row & 7) << 2)]) = u;
        }
    };

    // fragment load for one kc step (16 LDS) into the given register set
    auto ldfrag = [&](int kt, int kc, uint32_t a[2][4], uint32_t bb[4][2]) {
        const int k0 = kc * 8 + (lane & 3);
        #pragma unroll
        for (int mi = 0; mi < 2; mi++) {
            int r = wm * 32 + mi * 16 + g;
            a[mi][0] = As[r][k0 ^ swz];
            a[mi][1] = As[r + 8][k0 ^ swz];
            a[mi][2] = As[r][(k0 + 4) ^ swz];
            a[mi][3] = As[r + 8][(k0 + 4) ^ swz];
        }
        const int kb = kt * 32;
        #pragma unroll
        for (int ni = 0; ni < 4; ni++) {
            int c = wn * 32 + ni * 8 + g;
            bb[ni][0] = Bs[c][(kb + k0) ^ swz];
            bb[ni][1] = Bs[c][(kb + k0 + 4) ^ swz];
        }
    };

    lda(0); sta(0);
    __syncthreads();

    uint32_t af[2][2][4];   // double-buffered fragment registers
    uint32_t bf[2][4][2];

    #pragma unroll
    for (int kt = 0; kt < KTILES; kt++) {
        if (kt + 1 < KTILES) lda(kt + 1);   // global prefetch (covered by whole kt)

        ldfrag(kt, 0, af[0], bf[0]);        // prime the register pipeline
        #pragma unroll
        for (int kc = 0; kc < 4; kc++) {
            const int cur = kc & 1;
            if (kc < 3) ldfrag(kt, kc + 1, af[cur ^ 1], bf[cur ^ 1]);  // overlap w/ MMAs
            #pragma unroll
            for (int mi = 0; mi < 2; mi++)
                #pragma unroll
                for (int ni = 0; ni < 4; ni++)
                    mma_tf32(acc[mi][ni], af[cur][mi], bf[cur][ni]);
        }
        __syncthreads();
        if (kt + 1 < KTILES) {
            sta(kt + 1);
            __syncthreads();
        }
    }

    // ---- epilogue: +bias, store raw Y, count-weighted deterministic BN partials ----
    float (*sred)[4][64] = reinterpret_cast<float (*)[4][64]>(&As[0][0]);

    const int rbase = m0 + wm * 32 + g;
    float wgt[4];
    #pragma unroll
    for (int q = 0; q < 4; q++) wgt[q] = (float)g_cnt[rbase + q * 8];

    #pragma unroll
    for (int ni = 0; ni < 4; ni++) {
        int cl = wn * 32 + ni * 8 + 2 * (lane & 3);
        int c  = oc0 + cl;
        float b0 = bias[c], b1 = bias[c + 1];
        float s0 = 0.f, q0 = 0.f, s1 = 0.f, q1 = 0.f;
        #pragma unroll
        for (int mi = 0; mi < 2; mi++) {
            int r = m0 + wm * 32 + mi * 16 + g;
            float wA = wgt[mi * 2], wB = wgt[mi * 2 + 1];
            float v00 = acc[mi][ni][0] + b0;
            float v01 = acc[mi][ni][1] + b1;
            float v10 = acc[mi][ni][2] + b0;
            float v11 = acc[mi][ni][3] + b1;
            *reinterpret_cast<float2*>(Y + (size_t)r * OC + c)       = make_float2(v00, v01);
            *reinterpret_cast<float2*>(Y + (size_t)(r + 8) * OC + c) = make_float2(v10, v11);
            s0 += wA * v00 + wB * v10;  q0 += wA * v00 * v00 + wB * v10 * v10;
            s1 += wA * v01 + wB * v11;  q1 += wA * v01 * v01 + wB * v11 * v11;
        }
        #pragma unroll
        for (int o = 4; o < 32; o <<= 1) {
            s0 += __shfl_xor_sync(0xffffffffu, s0, o);
            q0 += __shfl_xor_sync(0xffffffffu, q0, o);
            s1 += __shfl_xor_sync(0xffffffffu, s1, o);
            q1 += __shfl_xor_sync(0xffffffffu, q1, o);
        }
        if (g == 0) {
            sred[0][wm][cl]     = s0;
            sred[1][wm][cl]     = q0;
            sred[0][wm][cl + 1] = s1;
            sred[1][wm][cl + 1] = q1;
        }
    }
    __syncthreads();
    if (tid < 128) {
        int part = tid >> 6, c = tid & 63;
        float s = sred[part][0][c] + sred[part][1][c] + sred[part][2][c] + sred[part][3][c];
        g_part[part][(size_t)(oc0 + c) * NSTATB + blockIdx.y] = s;
    }
}

// ---------------- stats stage 2: mean/var over gathered population ----------------
__global__ __launch_bounds__(256)
void stats_final_kernel(const float* __restrict__ gamma, const float* __restrict__ beta) {
    const int oc  = blockIdx.x;
    const int tid = threadIdx.x;
    float s = 0.f, s2 = 0.f;
    for (int i = tid; i < NSTATB; i += 256) {
        s  += g_part[0][(size_t)oc * NSTATB + i];
        s2 += g_part[1][(size_t)oc * NSTATB + i];
    }
    __shared__ float sh[2][256];
    sh[0][tid] = s; sh[1][tid] = s2;
    __syncthreads();
    for (int off = 128; off; off >>= 1) {
        if (tid < off) {
            sh[0][tid] += sh[0][tid + off];
            sh[1][tid] += sh[1][tid + off];
        }
        __syncthreads();
    }
    if (tid == 0) {
        float inv  = 1.0f / (float)M_TOTAL;
        float mean = sh[0][0] * inv;
        float var  = sh[1][0] * inv - mean * mean;
        float sc   = gamma[oc] / sqrtf(var + EPSV);
        g_scale[oc] = sc;
        g_shift[oc] = beta[oc] - mean * sc;
    }
}

// ---------------- final: gather Y2 rows, BN+ReLU, max over 32 samples ----------------
__global__ __launch_bounds__(256)
void maxpool_kernel(const float* __restrict__ Y2, float* __restrict__ outp) {
    __shared__ int sidx[NSAMPLE];
    const int bn  = blockIdx.x;
    const int b   = bn >> 10;
    const int tid = threadIdx.x;
    if (tid < NSAMPLE) sidx[tid] = g_idx[bn * NSAMPLE + tid];
    __syncthreads();
    const float sc = g_scale[tid], sh = g_shift[tid];
    float m = -3.4e38f;
    #pragma unroll
    for (int s = 0; s < NSAMPLE; s++) {
        size_t row = (size_t)(b * NPTS + sidx[s]);
        float v = fmaxf(fmaf(Y2[row * 256 + tid], sc, sh), 0.f);
        m = fmaxf(m, v);
    }
    outp[(size_t)bn * 256 + tid] = m;
}

// ---------------- launch ----------------
extern "C" void kernel_launch(void* const* d_in, const int* in_sizes, int n_in,
                              void* d_out, int out_size) {
    (void)in_sizes; (void)n_in; (void)out_size;
    const float* xyz = (const float*)d_in[0];
    const float* pts = (const float*)d_in[1];
    const int*   fps = (const int*)d_in[2];
    const float* w0  = (const float*)d_in[3];
    const float* b0  = (const float*)d_in[4];
    const float* gm0 = (const float*)d_in[5];
    const float* bt0 = (const float*)d_in[6];
    const float* w1  = (const float*)d_in[7];
    const float* b1  = (const float*)d_in[8];
    const float* gm1 = (const float*)d_in[9];
    const float* bt1 = (const float*)d_in[10];
    const float* w2  = (const float*)d_in[11];
    const float* b2  = (const float*)d_in[12];
    const float* gm2 = (const float*)d_in[13];
    const float* bt2 = (const float*)d_in[14];
    float* out = (float*)d_out;

    void *pX0, *pY0, *pY1, *pY2, *pSc, *pSh;
    cudaGetSymbolAddress(&pX0, g_X0);
    cudaGetSymbolAddress(&pY0, g_Y0);
    cudaGetSymbolAddress(&pY1, g_Y1);
    cudaGetSymbolAddress(&pY2, g_Y2);
    cudaGetSymbolAddress(&pSc, g_scale);
    cudaGetSymbolAddress(&pSh, g_shift);
    float* X0 = (float*)pX0;
    float* Y0 = (float*)pY0;
    float* Y1 = (float*)pY1;
    float* Y2 = (float*)pY2;
    const float* Sc = (const float*)pSc;
    const float* Sh = (const float*)pSh;

    prep_kernel<<<2048, 256>>>(xyz, pts);
    knn_kernel<<<BATCH * NPOINT, 256>>>(xyz, fps, out);

    gemm_tf32_kernel<3, false><<<dim3(1, MU / 128), 256>>>(
        X0, K0PAD, w0, 67, b0, nullptr, nullptr, Y0, 64);
    stats_final_kernel<<<64, 256>>>(gm0, bt0);

    gemm_tf32_kernel<2, true><<<dim3(2, MU / 128), 256>>>(
        Y0, 64, w1, 64, b1, Sc, Sh, Y1, 128);
    stats_final_kernel<<<128, 256>>>(gm1, bt1);

    gemm_tf32_kernel<4, true><<<dim3(4, MU / 128), 256>>>(
        Y1, 128, w2, 128, b2, Sc, Sh, Y2, 256);
    stats_final_kernel<<<256, 256>>>(gm2, bt2);

    maxpool_kernel<<<BATCH * NPOINT, 256>>>(Y2, out + NEWXYZ);
}

// round 13
// speedup vs baseline: 1.3158x; 1.0316x over previous
#include <cuda_runtime.h>
#include <cstdint>
#include <cstddef>

#define BATCH   8
#define NPTS    4096
#define NPOINT  1024
#define NSAMPLE 32
#define CFEAT   64
#define EPSV    1e-5f

constexpr int M_TOTAL = BATCH * NPOINT * NSAMPLE;   // 262144 (BN population)
constexpr int MU      = BATCH * NPTS;               // 32768 unique rows
constexpr int NEWXYZ  = BATCH * NPOINT * 3;         // 24576
constexpr int NSTATB  = MU / 128;                   // 256 partial blocks (= gemm grid.y)

// ---------------- device scratch ----------------
__device__ float g_Y0[(size_t)MU * 64];
__device__ float g_Y1[(size_t)MU * 128];
__device__ float g_Y2[(size_t)MU * 256];
__device__ int   g_cnt[MU];                         // occurrence histogram
__device__ int   g_idx[BATCH * NPOINT * NSAMPLE];   // selected neighbor ids (set, any order)
__device__ float g_part[2][256 * NSTATB];
__device__ float g_scale[256];
__device__ float g_shift[256];

// ---------------- helpers ----------------
__device__ __forceinline__ uint32_t cvt_tf32(float x) {
    uint32_t r; asm("cvt.rna.tf32.f32 %0, %1;" : "=r"(r) : "f"(x)); return r;
}
__device__ __forceinline__ void mma_tf32(float d[4], const uint32_t a[4], const uint32_t b[2]) {
    asm volatile("mma.sync.aligned.m16n8k8.row.col.f32.tf32.tf32.f32 "
                 "{%0,%1,%2,%3}, {%4,%5,%6,%7}, {%8,%9}, {%0,%1,%2,%3};"
                 : "+f"(d[0]), "+f"(d[1]), "+f"(d[2]), "+f"(d[3])
                 : "r"(a[0]), "r"(a[1]), "r"(a[2]), "r"(a[3]),
                   "r"(b[0]), "r"(b[1]));
}
__device__ __forceinline__ unsigned long long umin64(unsigned long long a, unsigned long long b) {
    return a < b ? a : b;
}

// ---------------- prep: zero occurrence histogram only ----------------
__global__ __launch_bounds__(256)
void prep_kernel() {
    int i = blockIdx.x * 256 + threadIdx.x;
    if (i < MU) g_cnt[i] = 0;
}

// ---------------- KNN via exact 2-level radix select (R7/R12-identical) ----------------
__global__ __launch_bounds__(256)
void knn_kernel(const float* __restrict__ xyz,
                const int*   __restrict__ fps,
                float*       __restrict__ out_newxyz) {
    __shared__ int hist[256];
    __shared__ unsigned long long cand[512];
    __shared__ int sel[NSAMPLE];
    __shared__ int s_bin, s_below;      // reused for both passes
    __shared__ int s_nsel, s_ncand, s_ovf;

    const int bn   = blockIdx.x;
    const int b    = bn >> 10;
    const int tid  = threadIdx.x;
    const int lane = tid & 31;
    const float* xb = xyz + (size_t)b * NPTS * 3;
    const int fi = fps[bn];
    const float cx = xb[fi * 3 + 0];
    const float cy = xb[fi * 3 + 1];
    const float cz = xb[fi * 3 + 2];
    if (tid == 0) {
        out_newxyz[bn * 3 + 0] = cx;
        out_newxyz[bn * 3 + 1] = cy;
        out_newxyz[bn * 3 + 2] = cz;
        s_nsel = 0; s_ncand = 0; s_ovf = 0;
    }
    if (tid < 256) hist[tid] = 0;
    __syncthreads();

    // keys in registers; d2 arithmetic order matches reference exactly
    unsigned long long key[16];
    #pragma unroll
    for (int j = 0; j < 16; j++) {
        int i = tid + j * 256;
        float dx = __fsub_rn(cx, xb[i * 3 + 0]);
        float dy = __fsub_rn(cy, xb[i * 3 + 1]);
        float dz = __fsub_rn(cz, xb[i * 3 + 2]);
        float d2 = __fadd_rn(__fadd_rn(__fmul_rn(dx, dx), __fmul_rn(dy, dy)), __fmul_rn(dz, dz));
        key[j] = ((unsigned long long)__float_as_uint(d2) << 32) | (unsigned)i;
        atomicAdd(&hist[(unsigned)(key[j] >> 55)], 1);          // exponent byte
    }
    __syncthreads();

    // warp 0: find exponent bin containing rank 32 (inclusive), count strictly below
    if (tid < 32) {
        int loc[8]; int s = 0;
        #pragma unroll
        for (int q = 0; q < 8; q++) { loc[q] = hist[lane * 8 + q]; s += loc[q]; }
        int incl = s;
        #pragma unroll
        for (int o = 1; o < 32; o <<= 1) {
            int v = __shfl_up_sync(0xffffffffu, incl, o);
            if (lane >= o) incl += v;
        }
        int excl = incl - s;
        unsigned bal = __ballot_sync(0xffffffffu, excl < NSAMPLE && NSAMPLE <= incl);
        if (lane == (int)(__ffs(bal) - 1)) {
            int c = excl;
            #pragma unroll
            for (int q = 0; q < 8; q++) {
                if (NSAMPLE <= c + loc[q]) { s_bin = lane * 8 + q; s_below = c; break; }
                c += loc[q];
            }
        }
    }
    __syncthreads();
    const int estar  = s_bin;
    const int below1 = s_below;
    if (tid < 256) hist[tid] = 0;
    __syncthreads();

    // pass 2: mantissa-byte histogram within exponent bin estar
    #pragma unroll
    for (int j = 0; j < 16; j++) {
        unsigned hi = (unsigned)(key[j] >> 32);
        if ((int)(hi >> 23) == estar)
            atomicAdd(&hist[(hi >> 15) & 0xFF], 1);
    }
    __syncthreads();
    const int R2 = NSAMPLE - below1;
    if (tid < 32) {
        int loc[8]; int s = 0;
        #pragma unroll
        for (int q = 0; q < 8; q++) { loc[q] = hist[lane * 8 + q]; s += loc[q]; }
        int incl = s;
        #pragma unroll
        for (int o = 1; o < 32; o <<= 1) {
            int v = __shfl_up_sync(0xffffffffu, incl, o);
            if (lane >= o) incl += v;
        }
        int excl = incl - s;
        unsigned bal = __ballot_sync(0xffffffffu, excl < R2 && R2 <= incl);
        if (lane == (int)(__ffs(bal) - 1)) {
            int c = excl;
            #pragma unroll
            for (int q = 0; q < 8; q++) {
                if (R2 <= c + loc[q]) { s_bin = lane * 8 + q; s_below = c; break; }
                c += loc[q];
            }
        }
    }
    __syncthreads();
    const int mstar  = s_bin;
    const int below2 = s_below;
    const int r2     = R2 - below2;        // 1..32, picked from boundary slice

    // direct-select strict-below prefix; boundary slice -> candidate list
    #pragma unroll
    for (int j = 0; j < 16; j++) {
        unsigned hi = (unsigned)(key[j] >> 32);
        int e = hi >> 23, m = (hi >> 15) & 0xFF;
        if (e < estar || (e == estar && m < mstar)) {
            int p = atomicAdd(&s_nsel, 1);
            sel[p] = (int)(key[j] & 0xffffffffu);
        } else if (e == estar && m == mstar) {
            int p = atomicAdd(&s_ncand, 1);
            if (p < 512) cand[p] = key[j]; else s_ovf = 1;
        }
    }
    __syncthreads();

    // tiny tournament: r2 smallest of the candidate slice (typically 1-4 entries)
    if (tid < 32) {
        int C = s_ncand < 512 ? s_ncand : 512;
        (void)s_ovf;
        for (int t = 0; t < r2; t++) {
            unsigned long long best = ~0ULL;
            for (int i = lane; i < C; i += 32) best = umin64(best, cand[i]);
            #pragma unroll
            for (int o = 16; o; o >>= 1)
                best = umin64(best, __shfl_xor_sync(0xffffffffu, best, o));
            for (int i = lane; i < C; i += 32)
                if (cand[i] == best) {                  // keys unique: one lane hits
                    cand[i] = ~0ULL;
                    sel[NSAMPLE - r2 + t] = (int)(best & 0xffffffffu);
                }
        }
    }
    __syncthreads();

    if (tid < NSAMPLE) {
        int pi = sel[tid];
        g_idx[bn * NSAMPLE + tid] = pi;
        atomicAdd(&g_cnt[b * NPTS + pi], 1);    // integer adds: deterministic
    }
}

// ---------------- TF32 GEMM: register-pipelined fragments ----------------
// L0: A = [pts(64) | xyz(3) | pad] read directly from inputs, W0 rows remapped.
template<int KTILES, bool AFF, bool L0>
__global__ __launch_bounds__(256, 2)
void gemm_tf32_kernel(const float* __restrict__ X, int ldx,
                      const float* __restrict__ xyz,
                      const float* __restrict__ W, int Kvalid,
                      const float* __restrict__ bias,
                      const float* __restrict__ scl,
                      const float* __restrict__ shf,
                      float* __restrict__ Y, int OC) {
    constexpr int KTOT = KTILES * 32;
    __shared__ uint32_t As[128][32];       // XOR-swizzled: col = k ^ ((row&7)<<2)
    __shared__ uint32_t Bs[64][KTOT];

    const int tid  = threadIdx.x;
    const int lane = tid & 31;
    const int wid  = tid >> 5;
    const int wm   = wid & 3;
    const int wn   = wid >> 2;
    const int m0   = blockIdx.y * 128;
    const int oc0  = blockIdx.x * 64;
    const int g    = lane >> 2;
    const int swz  = g << 2;

    for (int idx = tid; idx < 64 * KTOT; idx += 256) {
        int oc = idx / KTOT, k = idx - oc * KTOT;
        float wv;
        if (L0) {
            if (k < 64)      wv = W[(size_t)(oc0 + oc) * 67 + 3 + k];
            else if (k < 67) wv = W[(size_t)(oc0 + oc) * 67 + (k - 64)];
            else             wv = 0.f;
        } else {
            wv = (k < Kvalid) ? W[(size_t)(oc0 + oc) * Kvalid + k] : 0.f;
        }
        Bs[oc][k ^ ((oc & 7) << 2)] = cvt_tf32(wv);
    }

    float acc[2][4][4];
    #pragma unroll
    for (int i = 0; i < 2; i++)
        #pragma unroll
        for (int j = 0; j < 4; j++)
            #pragma unroll
            for (int k = 0; k < 4; k++) acc[i][j][k] = 0.f;

    float4 pf[4];
    auto lda = [&](int kt) {
        #pragma unroll
        for (int it = 0; it < 4; it++) {
            int idx = tid + it * 256;
            int row = idx >> 3, q = idx & 7;
            int kk  = kt * 32 + q * 4;
            int r   = m0 + row;
            if (L0) {
                if (kk < 64)
                    pf[it] = *reinterpret_cast<const float4*>(X + (size_t)r * 64 + kk);
                else if (kk == 64)
                    pf[it] = make_float4(xyz[(size_t)r * 3 + 0], xyz[(size_t)r * 3 + 1],
                                         xyz[(size_t)r * 3 + 2], 0.f);
                else
                    pf[it] = make_float4(0.f, 0.f, 0.f, 0.f);
            } else {
                pf[it] = (kk < ldx)
                    ? *reinterpret_cast<const float4*>(X + (size_t)r * ldx + kk)
                    : make_float4(0.f, 0.f, 0.f, 0.f);
            }
        }
    };
    auto sta = [&](int kt) {
        #pragma unroll
        for (int it = 0; it < 4; it++) {
            int idx = tid + it * 256;
            int row = idx >> 3, q = idx & 7;
            float4 v = pf[it];
            if (AFF) {
                int kk = kt * 32 + q * 4;
                if (kk < ldx) {
                    float4 s4 = *reinterpret_cast<const float4*>(scl + kk);
                    float4 h4 = *reinterpret_cast<const float4*>(shf + kk);
                    v.x = fmaxf(fmaf(v.x, s4.x, h4.x), 0.f);
                    v.y = fmaxf(fmaf(v.y, s4.y, h4.y), 0.f);
                    v.z = fmaxf(fmaf(v.z, s4.z, h4.z), 0.f);
                    v.w = fmaxf(fmaf(v.w, s4.w, h4.w), 0.f);
                }
            }
            uint4 u;
            u.x = cvt_tf32(v.x); u.y = cvt_tf32(v.y);
            u.z = cvt_tf32(v.z); u.w = cvt_tf32(v.w);
            *reinterpret_cast<uint4*>(&As[row][(q * 4) ^ ((row & 7) << 2)]) = u;
        }
    };

    // fragment load for one kc step (16 LDS) into the given register set
    auto ldfrag = [&](int kt, int kc, uint32_t a[2][4], uint32_t bb[4][2]) {
        const int k0 = kc * 8 + (lane & 3);
        #pragma unroll
        for (int mi = 0; mi < 2; mi++) {
            int r = wm * 32 + mi * 16 + g;
            a[mi][0] = As[r][k0 ^ swz];
            a[mi][1] = As[r + 8][k0 ^ swz];
            a[mi][2] = As[r][(k0 + 4) ^ swz];
            a[mi][3] = As[r + 8][(k0 + 4) ^ swz];
        }
        const int kb = kt * 32;
        #pragma unroll
        for (int ni = 0; ni < 4; ni++) {
            int c = wn * 32 + ni * 8 + g;
            bb[ni][0] = Bs[c][(kb + k0) ^ swz];
            bb[ni][1] = Bs[c][(kb + k0 + 4) ^ swz];
        }
    };

    lda(0); sta(0);
    __syncthreads();

    uint32_t af[2][2][4];   // double-buffered fragment registers
    uint32_t bf[2][4][2];

    #pragma unroll
    for (int kt = 0; kt < KTILES; kt++) {
        if (kt + 1 < KTILES) lda(kt + 1);   // global prefetch (covered by whole kt)

        ldfrag(kt, 0, af[0], bf[0]);        // prime the register pipeline
        #pragma unroll
        for (int kc = 0; kc < 4; kc++) {
            const int cur = kc & 1;
            if (kc < 3) ldfrag(kt, kc + 1, af[cur ^ 1], bf[cur ^ 1]);  // overlap w/ MMAs
            #pragma unroll
            for (int mi = 0; mi < 2; mi++)
                #pragma unroll
                for (int ni = 0; ni < 4; ni++)
                    mma_tf32(acc[mi][ni], af[cur][mi], bf[cur][ni]);
        }
        __syncthreads();
        if (kt + 1 < KTILES) {
            sta(kt + 1);
            __syncthreads();
        }
    }

    // ---- epilogue: +bias, store raw Y, count-weighted deterministic BN partials ----
    float (*sred)[4][64] = reinterpret_cast<float (*)[4][64]>(&As[0][0]);

    const int rbase = m0 + wm * 32 + g;
    float wgt[4];
    #pragma unroll
    for (int q = 0; q < 4; q++) wgt[q] = (float)g_cnt[rbase + q * 8];

    #pragma unroll
    for (int ni = 0; ni < 4; ni++) {
        int cl = wn * 32 + ni * 8 + 2 * (lane & 3);
        int c  = oc0 + cl;
        float b0 = bias[c], b1 = bias[c + 1];
        float s0 = 0.f, q0 = 0.f, s1 = 0.f, q1 = 0.f;
        #pragma unroll
        for (int mi = 0; mi < 2; mi++) {
            int r = m0 + wm * 32 + mi * 16 + g;
            float wA = wgt[mi * 2], wB = wgt[mi * 2 + 1];
            float v00 = acc[mi][ni][0] + b0;
            float v01 = acc[mi][ni][1] + b1;
            float v10 = acc[mi][ni][2] + b0;
            float v11 = acc[mi][ni][3] + b1;
            *reinterpret_cast<float2*>(Y + (size_t)r * OC + c)       = make_float2(v00, v01);
            *reinterpret_cast<float2*>(Y + (size_t)(r + 8) * OC + c) = make_float2(v10, v11);
            s0 += wA * v00 + wB * v10;  q0 += wA * v00 * v00 + wB * v10 * v10;
            s1 += wA * v01 + wB * v11;  q1 += wA * v01 * v01 + wB * v11 * v11;
        }
        #pragma unroll
        for (int o = 4; o < 32; o <<= 1) {
            s0 += __shfl_xor_sync(0xffffffffu, s0, o);
            q0 += __shfl_xor_sync(0xffffffffu, q0, o);
            s1 += __shfl_xor_sync(0xffffffffu, s1, o);
            q1 += __shfl_xor_sync(0xffffffffu, q1, o);
        }
        if (g == 0) {
            sred[0][wm][cl]     = s0;
            sred[1][wm][cl]     = q0;
            sred[0][wm][cl + 1] = s1;
            sred[1][wm][cl + 1] = q1;
        }
    }
    __syncthreads();
    if (tid < 128) {
        int part = tid >> 6, c = tid & 63;
        float s = sred[part][0][c] + sred[part][1][c] + sred[part][2][c] + sred[part][3][c];
        g_part[part][(size_t)(oc0 + c) * NSTATB + blockIdx.y] = s;
    }
}

// ---------------- stats stage 2: mean/var over gathered population ----------------
__global__ __launch_bounds__(256)
void stats_final_kernel(const float* __restrict__ gamma, const float* __restrict__ beta) {
    const int oc  = blockIdx.x;
    const int tid = threadIdx.x;
    float s = 0.f, s2 = 0.f;
    for (int i = tid; i < NSTATB; i += 256) {
        s  += g_part[0][(size_t)oc * NSTATB + i];
        s2 += g_part[1][(size_t)oc * NSTATB + i];
    }
    __shared__ float sh[2][256];
    sh[0][tid] = s; sh[1][tid] = s2;
    __syncthreads();
    for (int off = 128; off; off >>= 1) {
        if (tid < off) {
            sh[0][tid] += sh[0][tid + off];
            sh[1][tid] += sh[1][tid + off];
        }
        __syncthreads();
    }
    if (tid == 0) {
        float inv  = 1.0f / (float)M_TOTAL;
        float mean = sh[0][0] * inv;
        float var  = sh[1][0] * inv - mean * mean;
        float sc   = gamma[oc] / sqrtf(var + EPSV);
        g_scale[oc] = sc;
        g_shift[oc] = beta[oc] - mean * sc;
    }
}

// ---------------- final: gather Y2 rows, BN+ReLU, max over 32 samples ----------------
__global__ __launch_bounds__(256)
void maxpool_kernel(const float* __restrict__ Y2, float* __restrict__ outp) {
    __shared__ int sidx[NSAMPLE];
    const int bn  = blockIdx.x;
    const int b   = bn >> 10;
    const int tid = threadIdx.x;
    if (tid < NSAMPLE) sidx[tid] = g_idx[bn * NSAMPLE + tid];
    __syncthreads();
    const float sc = g_scale[tid], sh = g_shift[tid];
    float m = -3.4e38f;
    #pragma unroll
    for (int s = 0; s < NSAMPLE; s++) {
        size_t row = (size_t)(b * NPTS + sidx[s]);
        float v = fmaxf(fmaf(Y2[row * 256 + tid], sc, sh), 0.f);
        m = fmaxf(m, v);
    }
    outp[(size_t)bn * 256 + tid] = m;
}

// ---------------- launch ----------------
extern "C" void kernel_launch(void* const* d_in, const int* in_sizes, int n_in,
                              void* d_out, int out_size) {
    (void)in_sizes; (void)n_in; (void)out_size;
    const float* xyz = (const float*)d_in[0];
    const float* pts = (const float*)d_in[1];
    const int*   fps = (const int*)d_in[2];
    const float* w0  = (const float*)d_in[3];
    const float* b0  = (const float*)d_in[4];
    const float* gm0 = (const float*)d_in[5];
    const float* bt0 = (const float*)d_in[6];
    const float* w1  = (const float*)d_in[7];
    const float* b1  = (const float*)d_in[8];
    const float* gm1 = (const float*)d_in[9];
    const float* bt1 = (const float*)d_in[10];
    const float* w2  = (const float*)d_in[11];
    const float* b2  = (const float*)d_in[12];
    const float* gm2 = (const float*)d_in[13];
    const float* bt2 = (const float*)d_in[14];
    float* out = (float*)d_out;

    void *pY0, *pY1, *pY2, *pSc, *pSh;
    cudaGetSymbolAddress(&pY0, g_Y0);
    cudaGetSymbolAddress(&pY1, g_Y1);
    cudaGetSymbolAddress(&pY2, g_Y2);
    cudaGetSymbolAddress(&pSc, g_scale);
    cudaGetSymbolAddress(&pSh, g_shift);
    float* Y0 = (float*)pY0;
    float* Y1 = (float*)pY1;
    float* Y2 = (float*)pY2;
    const float* Sc = (const float*)pSc;
    const float* Sh = (const float*)pSh;

    prep_kernel<<<(MU + 255) / 256, 256>>>();
    knn_kernel<<<BATCH * NPOINT, 256>>>(xyz, fps, out);

    gemm_tf32_kernel<3, false, true><<<dim3(1, MU / 128), 256>>>(
        pts, 64, xyz, w0, 67, b0, nullptr, nullptr, Y0, 64);
    stats_final_kernel<<<64, 256>>>(gm0, bt0);

    gemm_tf32_kernel<2, true, false><<<dim3(2, MU / 128), 256>>>(
        Y0, 64, nullptr, w1, 64, b1, Sc, Sh, Y1, 128);
    stats_final_kernel<<<128, 256>>>(gm1, bt1);

    gemm_tf32_kernel<4, true, false><<<dim3(4, MU / 128), 256>>>(
        Y1, 128, nullptr, w2, 128, b2, Sc, Sh, Y2, 256);
    stats_final_kernel<<<256, 256>>>(gm2, bt2);

    maxpool_kernel<<<BATCH * NPOINT, 256>>>(Y2, out + NEWXYZ);
}